// round 14
// baseline (speedup 1.0000x reference)
#include <cuda_runtime.h>
#include <cuda_fp16.h>
#include <math.h>
#include <stdint.h>

#define VOCABN 128
#define HID    1024
#define BATCHN 256
#define SEQ    256
#define NCTA   128     // recurrence CTAs
#define NFC    20      // fc consumer CTAs
#define GRPSZ  16u

// ---------------- device scratch (no allocations allowed) ----------------
__device__ float    g_P[VOCABN * HID];
__device__ __half   g_hhi [(size_t)SEQ * BATCHN * HID];
__device__ __half   g_hlos[(size_t)SEQ * BATCHN * HID];
__device__ __half   g_whhhi[HID * HID], g_whhlos[HID * HID];
__device__ __half   g_wxhhi[HID * HID], g_wxhlos[HID * HID];
__device__ __half   g_embhi[VOCABN * HID], g_emblos[VOCABN * HID];
__device__ __half   g_fchi[VOCABN * HID],  g_fclos[VOCABN * HID];
__device__ unsigned g_bar[SEQ * 8];                  // per-(step, m-group) counters

// ---------------- PTX helpers ----------------
__device__ __forceinline__ uint32_t smem_u32(const void* p) {
    uint32_t a;
    asm("{ .reg .u64 t; cvta.to.shared.u64 t, %1; cvt.u32.u64 %0, t; }" : "=r"(a) : "l"(p));
    return a;
}
__device__ __forceinline__ uint32_t swz(uint32_t o) { return o ^ ((o >> 3) & 0x70); }

#define CP_ASYNC16(dst, src) \
    asm volatile("cp.async.cg.shared.global [%0], [%1], 16;" :: "r"(dst), "l"(src) : "memory")
#define CP_COMMIT() asm volatile("cp.async.commit_group;" ::: "memory")
#define CP_WAIT2()  asm volatile("cp.async.wait_group 2;" ::: "memory")
#define CP_WAIT1()  asm volatile("cp.async.wait_group 1;" ::: "memory")
#define CP_WAIT0()  asm volatile("cp.async.wait_group 0;" ::: "memory")

#define LDSM4(r, addr)                                                            \
    asm volatile("ldmatrix.sync.aligned.m8n8.x4.shared.b16 {%0,%1,%2,%3}, [%4];"  \
        : "=r"((r)[0]), "=r"((r)[1]), "=r"((r)[2]), "=r"((r)[3]) : "r"(addr))

// fp32-accumulate mma (main term — exact)
#define MMA16816(c, a, b0, b1)                                                    \
    asm volatile("mma.sync.aligned.m16n8k16.row.col.f32.f16.f16.f32 "             \
        "{%0,%1,%2,%3},{%4,%5,%6,%7},{%8,%9},{%0,%1,%2,%3};"                      \
        : "+f"((c)[0]), "+f"((c)[1]), "+f"((c)[2]), "+f"((c)[3])                   \
        : "r"((a)[0]), "r"((a)[1]), "r"((a)[2]), "r"((a)[3]), "r"(b0), "r"(b1))

// fp16-accumulate mma (correction terms)
#define MMA16816H(c, a, b0, b1)                                                   \
    asm volatile("mma.sync.aligned.m16n8k16.row.col.f16.f16.f16.f16 "             \
        "{%0,%1},{%2,%3,%4,%5},{%6,%7},{%0,%1};"                                  \
        : "+r"((c)[0]), "+r"((c)[1])                                              \
        : "r"((a)[0]), "r"((a)[1]), "r"((a)[2]), "r"((a)[3]), "r"(b0), "r"(b1))

// ===========================================================================
// RNN loaders. Big chunk = K=128 = two 16KB halves, slot = bk % 3 (32KB each).
// Half layout: [Ahi fp16 4KB | Alo fp16 4KB | Wlos fp16 8KB], all SW128.
// ===========================================================================
__device__ __forceinline__ void rnn_load_W2(
    uint32_t STG, int tid, int bk, const __half* __restrict__ Wlos, int n0)
{
    const uint32_t stg0 = STG + (uint32_t)(bk % 3) * 32768;
    const int r = tid >> 3, cc = tid & 7;
#pragma unroll
    for (int sub = 0; sub < 2; sub++) {
        const int kb = (bk * 2 + sub) * 64 + cc * 8;
        const uint32_t stg = stg0 + (uint32_t)sub * 16384;
        CP_ASYNC16(stg + 8192 + swz((uint32_t)(r * 128 + cc * 16)),
                   Wlos + (size_t)(n0 + r) * HID + kb);
        CP_ASYNC16(stg + 8192 + swz((uint32_t)((r + 32) * 128 + cc * 16)),
                   Wlos + (size_t)(n0 + r + 32) * HID + kb);
    }
    CP_COMMIT();
}

__device__ __forceinline__ void rnn_load_A2(
    uint32_t STG, int tid, int bk,
    const __half* __restrict__ Ahi, const __half* __restrict__ Alo, size_t m0)
{
    const uint32_t stg0 = STG + (uint32_t)(bk % 3) * 32768;
    const int r = tid >> 3, cc = tid & 7;
    const uint32_t off = swz((uint32_t)(r * 128 + cc * 16));
#pragma unroll
    for (int sub = 0; sub < 2; sub++) {
        const int kb = (bk * 2 + sub) * 64 + cc * 8;
        const uint32_t stg = stg0 + (uint32_t)sub * 16384;
        CP_ASYNC16(stg + off,        Ahi + (m0 + r) * (size_t)HID + kb);
        CP_ASYNC16(stg + 4096 + off, Alo + (m0 + r) * (size_t)HID + kb);
    }
    CP_COMMIT();
}

__device__ __forceinline__ void rnn_load_full2(
    uint32_t STG, int tid, int bk,
    const __half* __restrict__ Ahi, const __half* __restrict__ Alo,
    const __half* __restrict__ Wlos, size_t m0, int n0)
{
    const uint32_t stg0 = STG + (uint32_t)(bk % 3) * 32768;
    const int r = tid >> 3, cc = tid & 7;
    const uint32_t off = swz((uint32_t)(r * 128 + cc * 16));
#pragma unroll
    for (int sub = 0; sub < 2; sub++) {
        const int kb = (bk * 2 + sub) * 64 + cc * 8;
        const uint32_t stg = stg0 + (uint32_t)sub * 16384;
        CP_ASYNC16(stg + off,        Ahi + (m0 + r) * (size_t)HID + kb);
        CP_ASYNC16(stg + 4096 + off, Alo + (m0 + r) * (size_t)HID + kb);
        CP_ASYNC16(stg + 8192 + off, Wlos + (size_t)(n0 + r) * HID + kb);
        CP_ASYNC16(stg + 8192 + swz((uint32_t)((r + 32) * 128 + cc * 16)),
                   Wlos + (size_t)(n0 + r + 32) * HID + kb);
    }
    CP_COMMIT();
}

// ---- fc consumer loader: quarter unit, A = 64 rows, B = 128 rows ----
// Stage (24KB): [A 8KB | B 16KB]; 4 stages.
__device__ __forceinline__ void fc_load(
    uint32_t FST, int tid, int slot, int c,
    const __half* __restrict__ Ahi, const __half* __restrict__ Alos,
    const __half* __restrict__ Bhi, const __half* __restrict__ Blos)
{
    const int seg = c >> 4;
    const __half* A = (seg == 2) ? Alos : Ahi;
    const __half* B = (seg == 1) ? Blos : Bhi;
    const uint32_t stg = FST + (uint32_t)slot * 24576;
#pragma unroll
    for (int i = 0; i < 2; i++) {                     // A: 64 rows x 128B
        int id = tid + i * 256, r = id >> 3;
        uint32_t off = swz((uint32_t)(r * 128 + (id & 7) * 16));
        CP_ASYNC16(stg + off, A + (size_t)r * HID + (c & 15) * 64 + (id & 7) * 8);
    }
#pragma unroll
    for (int i = 0; i < 4; i++) {                     // B: 128 rows x 128B
        int id = tid + i * 256, r = id >> 3;
        uint32_t off = swz((uint32_t)(r * 128 + (id & 7) * 16));
        CP_ASYNC16(stg + 8192 + off, B + (size_t)r * HID + (c & 15) * 64 + (id & 7) * 8);
    }
    CP_COMMIT();
}

// ===========================================================================
// Fused persistent kernel: CTAs 0..127 recurrence (t=0 computed in prologue,
// published via flag slot t=0), CTAs 128..147 fc consumers (wait on flags for
// ALL t including t=0). Hidden output fused at t=255.
// ===========================================================================
__global__ __launch_bounds__(256, 1)
void k_fused(const __half* __restrict__ Whi, const __half* __restrict__ Wlos,
             const float* __restrict__ bias, const float* __restrict__ P,
             const int* __restrict__ x,
             __half* __restrict__ hhi, __half* __restrict__ hlos,
             const __half* __restrict__ FChi, const __half* __restrict__ FClos,
             const float* __restrict__ fcb, float* __restrict__ outp)
{
    extern __shared__ char smem_raw[];
    const uint32_t sb  = (smem_u32(smem_raw) + 1023u) & ~1023u;
    const int tid = threadIdx.x;
    const int wid = tid >> 5, lane = tid & 31;
    const size_t SLOT = (size_t)BATCHN * HID;

    if (blockIdx.x < NCTA) {
        // =================== RNN path ===================
        const uint32_t PIN = sb;                 // 16 x 8KB pinned Whi
        const uint32_t STG = sb + 131072;        // 3 x 32KB stages
        const int wm  = wid >> 2, wn = wid & 3;
        const int g   = lane >> 2, t4 = lane & 3;
        const int grp = blockIdx.x >> 4;
        const size_t m0 = (size_t)grp * 32;
        const int    n0 = (blockIdx.x & 15) * 64;

        // pin Whi slice
        {
            const int r = tid >> 3, cc = tid & 7;
#pragma unroll 1
            for (int k0 = 0; k0 < 16; k0++) {
#pragma unroll
                for (int p = 0; p < 2; p++) {
                    int rr = r + p * 32;
                    CP_ASYNC16(PIN + k0 * 8192 + swz((uint32_t)(rr * 128 + cc * 16)),
                               Whi + (size_t)(n0 + rr) * HID + k0 * 64 + cc * 8);
                }
            }
            CP_COMMIT(); CP_WAIT0();
        }
        __syncthreads();

        // ---- prologue: t = 0 slice (replaces k_step0 launch) ----
        {
#pragma unroll
            for (int j = 0; j < 8; j++) {
                const int e = tid * 8 + j;           // 2048 elems: 32 rows x 64 cols
                const int r = e >> 6, c = e & 63;
                const size_t m = m0 + r;
                const int    n = n0 + c;
                const float h = tanhf(P[(size_t)x[m * SEQ] * HID + n] + bias[n]);
                const __half a = __float2half_rn(h);
                hhi [m * HID + n] = a;
                hlos[m * HID + n] =
                    __float2half_rn((h - __half2float(a)) * 32.f);
            }
            __threadfence();
            __syncthreads();
            if (tid == 0)
                asm volatile("red.release.gpu.global.add.u32 [%0], %1;"
                             :: "l"(&g_bar[grp]), "r"(1u) : "memory");
        }

        float2 bb[2];
#pragma unroll
        for (int nf = 0; nf < 2; nf++) {
            int n = n0 + wn * 16 + nf * 8 + t4 * 2;
            bb[nf].x = bias[n]; bb[nf].y = bias[n + 1];
        }

        // W prefetch for chunk 0 of the first step (slot 0)
        rnn_load_W2(STG, tid, 0, Wlos, n0);

#pragma unroll 1
        for (int t = 1; t < SEQ; t++) {
            // wait for group (t-1) completion (t=1: slot set by prologue)
            if (tid == 0) {
                const unsigned* slot = &g_bar[(t - 1) * 8 + grp];
                unsigned v;
                while (true) {
                    asm volatile("ld.acquire.gpu.global.u32 %0, [%1];"
                                 : "=r"(v) : "l"(slot) : "memory");
                    if (v >= GRPSZ) break;
                    __nanosleep(32);
                }
            }
            __syncthreads();

            const __half* Ahi = hhi  + (size_t)(t - 1) * SLOT;
            const __half* Alo = hlos + (size_t)(t - 1) * SLOT;
            rnn_load_A2(STG, tid, 0, Ahi, Alo, m0);
            rnn_load_full2(STG, tid, 1, Ahi, Alo, Wlos, m0, n0);

            float    acc0[2][4];
            uint32_t ach1[2][2], ach2[2][2];
#pragma unroll
            for (int j = 0; j < 2; j++) {
#pragma unroll
                for (int q = 0; q < 4; q++) acc0[j][q] = 0.f;
                ach1[j][0] = 0u; ach1[j][1] = 0u;
                ach2[j][0] = 0u; ach2[j][1] = 0u;
            }

#pragma unroll 1
            for (int k = 0; k < 8; k++) {
                if (k < 7) CP_WAIT1(); else CP_WAIT0();
                __syncthreads();
                if (k + 2 < 8)
                    rnn_load_full2(STG, tid, k + 2, Ahi, Alo, Wlos, m0, n0);
                const uint32_t stg0 = STG + (uint32_t)(k % 3) * 32768;
#pragma unroll
                for (int sub = 0; sub < 2; sub++) {
                    const uint32_t stg  = stg0 + (uint32_t)sub * 16384;
                    const uint32_t pinc = PIN + (uint32_t)(k * 2 + sub) * 8192;
#pragma unroll
                    for (int kk = 0; kk < 4; kk++) {
                        uint32_t afh[4], afl[4], bfh[4], bfl[4];
                        {
                            const int r0 = wm * 16 + (lane & 15);
                            const int c2 = (kk * 16 + (lane >> 4) * 8) * 2;
                            const uint32_t off = swz((uint32_t)(r0 * 128 + c2));
                            LDSM4(afh, stg + off);
                            LDSM4(afl, stg + 4096 + off);
                        }
                        {
                            const int r0 = wn * 16 + (lane & 7) + ((lane >> 4) << 3);
                            const int c2 = (kk * 16 + ((lane >> 3) & 1) * 8) * 2;
                            const uint32_t off = swz((uint32_t)(r0 * 128 + c2));
                            LDSM4(bfh, pinc + off);
                            LDSM4(bfl, stg + 8192 + off);
                        }
                        MMA16816(acc0[0], afh, bfh[0], bfh[1]);   // hi*hi
                        MMA16816(acc0[1], afh, bfh[2], bfh[3]);
                        MMA16816H(ach1[0], afh, bfl[0], bfl[1]);  // hi*wlo
                        MMA16816H(ach1[1], afh, bfl[2], bfl[3]);
                        MMA16816H(ach2[0], afl, bfh[0], bfh[1]);  // lo*whi
                        MMA16816H(ach2[1], afl, bfh[2], bfh[3]);
                    }
                }
            }

            const size_t mr0 = m0 + wm * 16 + g;
            const int xr0 = x[mr0 * SEQ + t];
            const int xr1 = x[(mr0 + 8) * SEQ + t];
            const float* Pr[2] = { P + (size_t)xr0 * HID, P + (size_t)xr1 * HID };
            __half* dhi = hhi  + (size_t)t * SLOT;
            __half* dlo = hlos + (size_t)t * SLOT;
            float* hid = outp + (size_t)BATCHN * SEQ * VOCABN;
#pragma unroll
            for (int nf = 0; nf < 2; nf++) {
                const int n = n0 + wn * 16 + nf * 8 + t4 * 2;
#pragma unroll
                for (int h2 = 0; h2 < 2; h2++) {
                    const size_t m = mr0 + h2 * 8;
                    const __half2 c1 = *reinterpret_cast<const __half2*>(&ach1[nf][h2]);
                    const __half2 c2 = *reinterpret_cast<const __half2*>(&ach2[nf][h2]);
                    float v0 = acc0[nf][h2 * 2] +
                               0.03125f * (__low2float(c1)  + __low2float(c2)) +
                               bb[nf].x + Pr[h2][n];
                    float v1 = acc0[nf][h2 * 2 + 1] +
                               0.03125f * (__high2float(c1) + __high2float(c2)) +
                               bb[nf].y + Pr[h2][n + 1];
                    const float h0 = tanhf(v0), h1 = tanhf(v1);
                    const __half a0 = __float2half_rn(h0), a1 = __float2half_rn(h1);
                    const float f0 = __half2float(a0), f1 = __half2float(a1);
                    *(__half2*)(dhi + m * HID + n) = __halves2half2(a0, a1);
                    *(__half2*)(dlo + m * HID + n) =
                        __halves2half2(__float2half_rn((h0 - f0) * 32.f),
                                       __float2half_rn((h1 - f1) * 32.f));
                    if (t == SEQ - 1) {
                        float2 o; o.x = h0; o.y = h1;
                        *(float2*)(hid + m * HID + n) = o;
                    }
                }
            }

            // publish first, then prefetch next step's W
            __threadfence();
            __syncthreads();
            if (tid == 0)
                asm volatile("red.release.gpu.global.add.u32 [%0], %1;"
                             :: "l"(&g_bar[t * 8 + grp]), "r"(1u) : "memory");
            if (t + 1 < SEQ)
                rnn_load_W2(STG, tid, 0, Wlos, n0);
        }
        return;
    }

    // ======================= fc consumer path (quarter units) =============
    const int cta = blockIdx.x - NCTA;
    const uint32_t FST = sb;                       // 4 stages x 24KB
    const int wm = wid >> 1, wn = wid & 1;         // 4 x 2 warps: tile 16 x 64
    const int g = lane >> 2, t4 = lane & 3;

#pragma unroll 1
    for (int u = cta; u < 4 * SEQ; u += NFC) {
        const int t = u >> 2, bh = u & 3;          // A rows [bh*64, bh*64+64)

        // wait on producer flags for ALL t (t=0 is published by the prologue)
        if (tid < 2) {                             // producers: m-groups 2bh, 2bh+1
            const unsigned* slot = &g_bar[t * 8 + bh * 2 + tid];
            unsigned v;
            while (true) {
                asm volatile("ld.acquire.gpu.global.u32 %0, [%1];"
                             : "=r"(v) : "l"(slot) : "memory");
                if (v >= GRPSZ) break;
                __nanosleep(128);
            }
        }
        __syncthreads();

        const __half* Ah = hhi  + (size_t)t * SLOT + (size_t)bh * 64 * HID;
        const __half* Al = hlos + (size_t)t * SLOT + (size_t)bh * 64 * HID;

        fc_load(FST, tid, 0, 0, Ah, Al, FChi, FClos);
        fc_load(FST, tid, 1, 1, Ah, Al, FChi, FClos);
        fc_load(FST, tid, 2, 2, Ah, Al, FChi, FClos);

        float    accA[8][4];
        uint32_t accBh[8][2];
#pragma unroll
        for (int j = 0; j < 8; j++) {
#pragma unroll
            for (int q = 0; q < 4; q++) accA[j][q] = 0.f;
            accBh[j][0] = 0u; accBh[j][1] = 0u;
        }

#pragma unroll 1
        for (int c = 0; c < 48; c++) {
            if (c < 46)       CP_WAIT2();
            else if (c == 46) CP_WAIT1();
            else              CP_WAIT0();
            __syncthreads();
            if (c + 3 < 48)
                fc_load(FST, tid, (c + 3) & 3, c + 3, Ah, Al, FChi, FClos);

            const uint32_t stg = FST + (uint32_t)(c & 3) * 24576;
            const bool mainseg = (c >> 4) == 0;
#pragma unroll
            for (int kk = 0; kk < 4; kk++) {
                uint32_t af[4], bf[4][4];
                {
                    const int r0 = wm * 16 + (lane & 15);
                    const int c2 = (kk * 16 + (lane >> 4) * 8) * 2;
                    LDSM4(af, stg + swz((uint32_t)(r0 * 128 + c2)));
                }
                {
                    const int r0 = wn * 64 + (lane & 7) + ((lane >> 4) << 3);
                    const int c2 = (kk * 16 + ((lane >> 3) & 1) * 8) * 2;
#pragma unroll
                    for (int np = 0; np < 4; np++)
                        LDSM4(bf[np], stg + 8192 +
                                      swz((uint32_t)((r0 + np * 16) * 128 + c2)));
                }
                if (mainseg) {
#pragma unroll
                    for (int np = 0; np < 4; np++) {
                        MMA16816(accA[np * 2],     af, bf[np][0], bf[np][1]);
                        MMA16816(accA[np * 2 + 1], af, bf[np][2], bf[np][3]);
                    }
                } else {
#pragma unroll
                    for (int np = 0; np < 4; np++) {
                        MMA16816H(accBh[np * 2],     af, bf[np][0], bf[np][1]);
                        MMA16816H(accBh[np * 2 + 1], af, bf[np][2], bf[np][3]);
                    }
                }
            }
        }

#pragma unroll
        for (int nf = 0; nf < 8; nf++) {
            const int n = wn * 64 + (nf >> 1) * 16 + (nf & 1) * 8 + t4 * 2;
            const float b0 = fcb[n], b1 = fcb[n + 1];
#pragma unroll
            for (int h2 = 0; h2 < 2; h2++) {
                const int mloc = wm * 16 + g + h2 * 8;
                const size_t b = (size_t)bh * 64 + mloc;
                const __half2 cb = *reinterpret_cast<const __half2*>(&accBh[nf][h2]);
                float2 o;
                o.x = accA[nf][h2 * 2]     + 0.03125f * __low2float(cb)  + b0;
                o.y = accA[nf][h2 * 2 + 1] + 0.03125f * __high2float(cb) + b1;
                *(float2*)(outp + (b * SEQ + t) * VOCABN + n) = o;
            }
        }
        __syncthreads();
    }
}

// ===========================================================================
// Generic streaming 3-split GEMM (P precompute only) — unchanged.
// ===========================================================================
__device__ __forceinline__ void wait_chunk(int k0) {
    if (k0 < 14)       CP_WAIT2();
    else if (k0 == 14) CP_WAIT1();
    else               CP_WAIT0();
}

template<int BM, int BN>
__device__ __forceinline__ void g3_load(
    uint32_t STG, int tid, int k0, size_t m0, int n0,
    const __half* __restrict__ Ahi, const __half* __restrict__ Alos,
    const __half* __restrict__ Bhi, const __half* __restrict__ Blos)
{
    constexpr int STAGE = (2 * BM + 2 * BN) * 128;
    const uint32_t stg = STG + (uint32_t)(k0 & 3) * STAGE;
#pragma unroll
    for (int i = 0; i < BM * 8 / 256; i++) {
        int id = tid + i * 256, r = id >> 3, cc = id & 7;
        int kb = k0 * 64 + cc * 8;
        uint32_t off = swz((uint32_t)(r * 128 + cc * 16));
        CP_ASYNC16(stg + off,            Ahi  + (m0 + r) * (size_t)HID + kb);
        CP_ASYNC16(stg + BM * 128 + off, Alos + (m0 + r) * (size_t)HID + kb);
    }
#pragma unroll
    for (int i = 0; i < BN * 8 / 256; i++) {
        int id = tid + i * 256, r = id >> 3, cc = id & 7;
        int kb = k0 * 64 + cc * 8;
        uint32_t off = swz((uint32_t)(r * 128 + cc * 16));
        CP_ASYNC16(stg + 2 * BM * 128 + off,            Bhi  + (size_t)(n0 + r) * HID + kb);
        CP_ASYNC16(stg + 2 * BM * 128 + BN * 128 + off, Blos + (size_t)(n0 + r) * HID + kb);
    }
    CP_COMMIT();
}

template<int BM, int BN, int WM, int WN>
__global__ __launch_bounds__(256, 1)
void k_g3(const __half* __restrict__ Ahi, const __half* __restrict__ Alos,
          const __half* __restrict__ Bhi, const __half* __restrict__ Blos,
          const float* __restrict__ bias, float* __restrict__ Cf)
{
    constexpr int TM = BM / WM, TN = BN / WN;
    constexpr int MF = TM / 16, NF2 = TN / 16;
    constexpr int STAGE = (2 * BM + 2 * BN) * 128;

    extern __shared__ char smem_raw[];
    const uint32_t sb = (smem_u32(smem_raw) + 1023u) & ~1023u;
    const int tid = threadIdx.x, wid = tid >> 5, lane = tid & 31;
    const int wm = wid / WN, wn = wid % WN;
    const int n0 = blockIdx.x * BN;
    const size_t m0 = (size_t)blockIdx.y * BM;

    float acc[3][MF][NF2 * 2][4];
#pragma unroll
    for (int s = 0; s < 3; s++)
#pragma unroll
        for (int i = 0; i < MF; i++)
#pragma unroll
            for (int j = 0; j < NF2 * 2; j++)
#pragma unroll
                for (int q = 0; q < 4; q++) acc[s][i][j][q] = 0.f;

    g3_load<BM, BN>(sb, tid, 0, m0, n0, Ahi, Alos, Bhi, Blos);
    g3_load<BM, BN>(sb, tid, 1, m0, n0, Ahi, Alos, Bhi, Blos);
    g3_load<BM, BN>(sb, tid, 2, m0, n0, Ahi, Alos, Bhi, Blos);

#pragma unroll 1
    for (int k0 = 0; k0 < 16; k0++) {
        wait_chunk(k0);
        __syncthreads();
        if (k0 + 3 < 16)
            g3_load<BM, BN>(sb, tid, k0 + 3, m0, n0, Ahi, Alos, Bhi, Blos);
        const uint32_t stg = sb + (uint32_t)(k0 & 3) * STAGE;
        const uint32_t aH = stg, aL = stg + BM * 128;
        const uint32_t bH = stg + 2 * BM * 128, bL = bH + BN * 128;
#pragma unroll
        for (int kk = 0; kk < 4; kk++) {
            uint32_t afh[MF][4], afl[MF][4], bfh[NF2][4], bfl[NF2][4];
            {
                const int r0 = wm * TM + (lane & 15);
                const int c2 = (kk * 16 + (lane >> 4) * 8) * 2;
#pragma unroll
                for (int mf = 0; mf < MF; mf++) {
                    uint32_t off = swz((uint32_t)((r0 + mf * 16) * 128 + c2));
                    LDSM4(afh[mf], aH + off);
                    LDSM4(afl[mf], aL + off);
                }
            }
            {
                const int r0 = wn * TN + (lane & 7) + ((lane >> 4) << 3);
                const int c2 = (kk * 16 + ((lane >> 3) & 1) * 8) * 2;
#pragma unroll
                for (int np = 0; np < NF2; np++) {
                    uint32_t off = swz((uint32_t)((r0 + np * 16) * 128 + c2));
                    LDSM4(bfh[np], bH + off);
                    LDSM4(bfl[np], bL + off);
                }
            }
#pragma unroll
            for (int mf = 0; mf < MF; mf++)
#pragma unroll
                for (int np = 0; np < NF2; np++) {
                    MMA16816(acc[0][mf][np * 2],     afh[mf], bfh[np][0], bfh[np][1]);
                    MMA16816(acc[0][mf][np * 2 + 1], afh[mf], bfh[np][2], bfh[np][3]);
                    MMA16816(acc[1][mf][np * 2],     afh[mf], bfl[np][0], bfl[np][1]);
                    MMA16816(acc[1][mf][np * 2 + 1], afh[mf], bfl[np][2], bfl[np][3]);
                    MMA16816(acc[2][mf][np * 2],     afl[mf], bfh[np][0], bfh[np][1]);
                    MMA16816(acc[2][mf][np * 2 + 1], afl[mf], bfh[np][2], bfh[np][3]);
                }
        }
    }

    const int g = lane >> 2, t4 = lane & 3;
#pragma unroll
    for (int mf = 0; mf < MF; mf++) {
#pragma unroll
        for (int nf = 0; nf < NF2 * 2; nf++) {
            const int n = n0 + wn * TN + (nf >> 1) * 16 + (nf & 1) * 8 + t4 * 2;
            const float b0 = bias[n], b1 = bias[n + 1];
#pragma unroll
            for (int h2 = 0; h2 < 2; h2++) {
                const size_t m = m0 + wm * TM + mf * 16 + g + h2 * 8;
                float2 o;
                o.x = acc[0][mf][nf][h2 * 2] +
                      0.03125f * (acc[1][mf][nf][h2 * 2] + acc[2][mf][nf][h2 * 2]) + b0;
                o.y = acc[0][mf][nf][h2 * 2 + 1] +
                      0.03125f * (acc[1][mf][nf][h2 * 2 + 1] + acc[2][mf][nf][h2 * 2 + 1]) + b1;
                *(float2*)(Cf + m * HID + n) = o;
            }
        }
    }
}

// ---------------- small kernels ----------------
// merged split + barrier reset
__global__ __launch_bounds__(256)
void k_split_all(const float* __restrict__ whh, __half* __restrict__ whhhi,
                 __half* __restrict__ whhlos,
                 const float* __restrict__ wxh, __half* __restrict__ wxhhi,
                 __half* __restrict__ wxhlos,
                 const float* __restrict__ fcw, __half* __restrict__ fchi,
                 __half* __restrict__ fclos,
                 const float* __restrict__ emb, __half* __restrict__ embhi,
                 __half* __restrict__ emblos)
{
    int i = blockIdx.x * 256 + threadIdx.x;
    if (i < SEQ * 8) g_bar[i] = 0;
    {
        float v = whh[i];
        __half h = __float2half_rn(v);
        whhhi[i]  = h;
        whhlos[i] = __float2half_rn((v - __half2float(h)) * 32.f);
    }
    {
        float v = wxh[i];
        __half h = __float2half_rn(v);
        wxhhi[i]  = h;
        wxhlos[i] = __float2half_rn((v - __half2float(h)) * 32.f);
    }
    if (i < VOCABN * HID) {
        {
            float v = fcw[i];
            __half h = __float2half_rn(v);
            fchi[i]  = h;
            fclos[i] = __float2half_rn((v - __half2float(h)) * 32.f);
        }
        {
            float v = emb[i];
            __half h = __float2half_rn(v);
            embhi[i]  = h;
            emblos[i] = __float2half_rn((v - __half2float(h)) * 32.f);
        }
    }
}

extern "C" void kernel_launch(void* const* d_in, const int* in_sizes, int n_in,
                              void* d_out, int out_size)
{
    const int*   x     = (const int*)  d_in[0];
    const float* embed = (const float*)d_in[1];
    const float* Wxh_w = (const float*)d_in[2];
    const float* Wxh_b = (const float*)d_in[3];
    const float* Whh_w = (const float*)d_in[4];
    const float* Whh_b = (const float*)d_in[5];
    const float* fc_w  = (const float*)d_in[6];
    const float* fc_b  = (const float*)d_in[7];
    float* outp = (float*)d_out;

    float* P;
    __half *hhi, *hlos, *whhhi, *whhlos, *wxhhi, *wxhlos, *embhi, *emblos, *fchi, *fclos;
    cudaGetSymbolAddress((void**)&P,      g_P);
    cudaGetSymbolAddress((void**)&hhi,    g_hhi);
    cudaGetSymbolAddress((void**)&hlos,   g_hlos);
    cudaGetSymbolAddress((void**)&whhhi,  g_whhhi);
    cudaGetSymbolAddress((void**)&whhlos, g_whhlos);
    cudaGetSymbolAddress((void**)&wxhhi,  g_wxhhi);
    cudaGetSymbolAddress((void**)&wxhlos, g_wxhlos);
    cudaGetSymbolAddress((void**)&embhi,  g_embhi);
    cudaGetSymbolAddress((void**)&emblos, g_emblos);
    cudaGetSymbolAddress((void**)&fchi,   g_fchi);
    cudaGetSymbolAddress((void**)&fclos,  g_fclos);

    const int SM_P   = (2 * 32 + 2 * 64) * 128 * 4 + 1024;    //  97 KB
    const int SM_RNN = 131072 + 3 * 32768 + 1024;             // 225 KB (fc path: 97 KB)
    cudaFuncSetAttribute(k_g3<32, 64, 2, 4>,
                         cudaFuncAttributeMaxDynamicSharedMemorySize, SM_P);
    cudaFuncSetAttribute(k_fused,
                         cudaFuncAttributeMaxDynamicSharedMemorySize, SM_RNN);

    // 0) operand splits + barrier reset (single kernel)
    k_split_all<<<(HID * HID) / 256, 256>>>(Whh_w, whhhi, whhlos,
                                            Wxh_w, wxhhi, wxhlos,
                                            fc_w, fchi, fclos,
                                            embed, embhi, emblos);

    // 1) P = embed @ Wxh^T + bxh
    k_g3<32, 64, 2, 4><<<dim3(HID / 64, VOCABN / 32), 256, SM_P>>>(
        embhi, emblos, wxhhi, wxhlos, Wxh_b, P);

    // 2) fused persistent: t=0 prologue + recurrence + fc consumers + hidden
    k_fused<<<NCTA + NFC, 256, SM_RNN>>>(whhhi, whhlos, Whh_b, P, x, hhi, hlos,
                                         fchi, fclos, fc_b, outp);
}

// round 15
// speedup vs baseline: 1.0402x; 1.0402x over previous
#include <cuda_runtime.h>
#include <cuda_fp16.h>
#include <math.h>
#include <stdint.h>

#define VOCABN 128
#define HID    1024
#define BATCHN 256
#define SEQ    256
#define NCTA   128     // recurrence CTAs
#define NFC    20      // fc consumer CTAs
#define GRPSZ  16u
#define TFC    240     // fc consumers cover t < TFC; rnn CTAs cover the rest

// ---------------- device scratch (no allocations allowed) ----------------
__device__ float    g_P[VOCABN * HID];
__device__ __half   g_hhi [(size_t)SEQ * BATCHN * HID];
__device__ __half   g_hlos[(size_t)SEQ * BATCHN * HID];
__device__ __half   g_whhhi[HID * HID], g_whhlos[HID * HID];
__device__ __half   g_wxhhi[HID * HID], g_wxhlos[HID * HID];
__device__ __half   g_embhi[VOCABN * HID], g_emblos[VOCABN * HID];
__device__ __half   g_fchi[VOCABN * HID],  g_fclos[VOCABN * HID];
__device__ unsigned g_bar[SEQ * 8];                  // per-(step, m-group) counters

// ---------------- PTX helpers ----------------
__device__ __forceinline__ uint32_t smem_u32(const void* p) {
    uint32_t a;
    asm("{ .reg .u64 t; cvta.to.shared.u64 t, %1; cvt.u32.u64 %0, t; }" : "=r"(a) : "l"(p));
    return a;
}
__device__ __forceinline__ uint32_t swz(uint32_t o) { return o ^ ((o >> 3) & 0x70); }

#define CP_ASYNC16(dst, src) \
    asm volatile("cp.async.cg.shared.global [%0], [%1], 16;" :: "r"(dst), "l"(src) : "memory")
#define CP_COMMIT() asm volatile("cp.async.commit_group;" ::: "memory")
#define CP_WAIT2()  asm volatile("cp.async.wait_group 2;" ::: "memory")
#define CP_WAIT1()  asm volatile("cp.async.wait_group 1;" ::: "memory")
#define CP_WAIT0()  asm volatile("cp.async.wait_group 0;" ::: "memory")

#define LDSM4(r, addr)                                                            \
    asm volatile("ldmatrix.sync.aligned.m8n8.x4.shared.b16 {%0,%1,%2,%3}, [%4];"  \
        : "=r"((r)[0]), "=r"((r)[1]), "=r"((r)[2]), "=r"((r)[3]) : "r"(addr))

// fp32-accumulate mma (main term — exact)
#define MMA16816(c, a, b0, b1)                                                    \
    asm volatile("mma.sync.aligned.m16n8k16.row.col.f32.f16.f16.f32 "             \
        "{%0,%1,%2,%3},{%4,%5,%6,%7},{%8,%9},{%0,%1,%2,%3};"                      \
        : "+f"((c)[0]), "+f"((c)[1]), "+f"((c)[2]), "+f"((c)[3])                   \
        : "r"((a)[0]), "r"((a)[1]), "r"((a)[2]), "r"((a)[3]), "r"(b0), "r"(b1))

// fp16-accumulate mma (correction terms)
#define MMA16816H(c, a, b0, b1)                                                   \
    asm volatile("mma.sync.aligned.m16n8k16.row.col.f16.f16.f16.f16 "             \
        "{%0,%1},{%2,%3,%4,%5},{%6,%7},{%0,%1};"                                  \
        : "+r"((c)[0]), "+r"((c)[1])                                              \
        : "r"((a)[0]), "r"((a)[1]), "r"((a)[2]), "r"((a)[3]), "r"(b0), "r"(b1))

__device__ __forceinline__ void poll_group(const unsigned* slot, int sleep_ns) {
    unsigned v;
    while (true) {
        asm volatile("ld.acquire.gpu.global.u32 %0, [%1];"
                     : "=r"(v) : "l"(slot) : "memory");
        if (v >= GRPSZ) break;
        __nanosleep(sleep_ns);
    }
}

// ===========================================================================
// RNN loaders. Big chunk = K=128 = two 16KB halves, slot = bk % 3 (32KB each).
// Half layout: [Ahi fp16 4KB | Alo fp16 4KB | Wlos fp16 8KB], all SW128.
// ===========================================================================
__device__ __forceinline__ void rnn_load_W2(
    uint32_t STG, int tid, int bk, const __half* __restrict__ Wlos, int n0)
{
    const uint32_t stg0 = STG + (uint32_t)(bk % 3) * 32768;
    const int r = tid >> 3, cc = tid & 7;
#pragma unroll
    for (int sub = 0; sub < 2; sub++) {
        const int kb = (bk * 2 + sub) * 64 + cc * 8;
        const uint32_t stg = stg0 + (uint32_t)sub * 16384;
        CP_ASYNC16(stg + 8192 + swz((uint32_t)(r * 128 + cc * 16)),
                   Wlos + (size_t)(n0 + r) * HID + kb);
        CP_ASYNC16(stg + 8192 + swz((uint32_t)((r + 32) * 128 + cc * 16)),
                   Wlos + (size_t)(n0 + r + 32) * HID + kb);
    }
    CP_COMMIT();
}

__device__ __forceinline__ void rnn_load_A2(
    uint32_t STG, int tid, int bk,
    const __half* __restrict__ Ahi, const __half* __restrict__ Alo, size_t m0)
{
    const uint32_t stg0 = STG + (uint32_t)(bk % 3) * 32768;
    const int r = tid >> 3, cc = tid & 7;
    const uint32_t off = swz((uint32_t)(r * 128 + cc * 16));
#pragma unroll
    for (int sub = 0; sub < 2; sub++) {
        const int kb = (bk * 2 + sub) * 64 + cc * 8;
        const uint32_t stg = stg0 + (uint32_t)sub * 16384;
        CP_ASYNC16(stg + off,        Ahi + (m0 + r) * (size_t)HID + kb);
        CP_ASYNC16(stg + 4096 + off, Alo + (m0 + r) * (size_t)HID + kb);
    }
    CP_COMMIT();
}

__device__ __forceinline__ void rnn_load_full2(
    uint32_t STG, int tid, int bk,
    const __half* __restrict__ Ahi, const __half* __restrict__ Alo,
    const __half* __restrict__ Wlos, size_t m0, int n0)
{
    const uint32_t stg0 = STG + (uint32_t)(bk % 3) * 32768;
    const int r = tid >> 3, cc = tid & 7;
    const uint32_t off = swz((uint32_t)(r * 128 + cc * 16));
#pragma unroll
    for (int sub = 0; sub < 2; sub++) {
        const int kb = (bk * 2 + sub) * 64 + cc * 8;
        const uint32_t stg = stg0 + (uint32_t)sub * 16384;
        CP_ASYNC16(stg + off,        Ahi + (m0 + r) * (size_t)HID + kb);
        CP_ASYNC16(stg + 4096 + off, Alo + (m0 + r) * (size_t)HID + kb);
        CP_ASYNC16(stg + 8192 + off, Wlos + (size_t)(n0 + r) * HID + kb);
        CP_ASYNC16(stg + 8192 + swz((uint32_t)((r + 32) * 128 + cc * 16)),
                   Wlos + (size_t)(n0 + r + 32) * HID + kb);
    }
    CP_COMMIT();
}

// ---- fc consumer loader: half unit, A = 128 rows, B = 128 rows ----
// Stage (32KB): [A 16KB | B 16KB]; 4 stages.
__device__ __forceinline__ void fc_load(
    uint32_t FST, int tid, int slot, int c,
    const __half* __restrict__ Ahi, const __half* __restrict__ Alos,
    const __half* __restrict__ Bhi, const __half* __restrict__ Blos)
{
    const int seg = c >> 4;
    const __half* A = (seg == 2) ? Alos : Ahi;
    const __half* B = (seg == 1) ? Blos : Bhi;
    const uint32_t stg = FST + (uint32_t)slot * 32768;
#pragma unroll
    for (int i = 0; i < 4; i++) {
        int id = tid + i * 256, r = id >> 3;
        uint32_t off = swz((uint32_t)(r * 128 + (id & 7) * 16));
        CP_ASYNC16(stg + off, A + (size_t)r * HID + (c & 15) * 64 + (id & 7) * 8);
    }
#pragma unroll
    for (int i = 0; i < 4; i++) {
        int id = tid + i * 256, r = id >> 3;
        uint32_t off = swz((uint32_t)(r * 128 + (id & 7) * 16));
        CP_ASYNC16(stg + 16384 + off, B + (size_t)r * HID + (c & 15) * 64 + (id & 7) * 8);
    }
    CP_COMMIT();
}

// ---- tail fc loader: A = 32 rows, B = 128 rows. Stage 20KB x 4. ----
__device__ __forceinline__ void tail_load(
    uint32_t FST, int tid, int slot, int c,
    const __half* __restrict__ Ahi, const __half* __restrict__ Alos,
    const __half* __restrict__ Bhi, const __half* __restrict__ Blos)
{
    const int seg = c >> 4;
    const __half* A = (seg == 2) ? Alos : Ahi;
    const __half* B = (seg == 1) ? Blos : Bhi;
    const uint32_t stg = FST + (uint32_t)slot * 20480;
    {   // A: 32 rows x 128B, exactly 1 cp.async/thread
        int r = tid >> 3;
        uint32_t off = swz((uint32_t)(r * 128 + (tid & 7) * 16));
        CP_ASYNC16(stg + off, A + (size_t)r * HID + (c & 15) * 64 + (tid & 7) * 8);
    }
#pragma unroll
    for (int i = 0; i < 4; i++) {                     // B: 128 rows x 128B
        int id = tid + i * 256, r = id >> 3;
        uint32_t off = swz((uint32_t)(r * 128 + (id & 7) * 16));
        CP_ASYNC16(stg + 4096 + off, B + (size_t)r * HID + (c & 15) * 64 + (id & 7) * 8);
    }
    CP_COMMIT();
}

// ===========================================================================
// Fused persistent kernel: CTAs 0..127 recurrence (round-12 verbatim) then a
// tail-fc sliver each; CTAs 128..147 fc consumers for t < TFC.
// ===========================================================================
__global__ __launch_bounds__(256, 1)
void k_fused(const __half* __restrict__ Whi, const __half* __restrict__ Wlos,
             const float* __restrict__ bias, const float* __restrict__ P,
             const int* __restrict__ x,
             __half* __restrict__ hhi, __half* __restrict__ hlos,
             const __half* __restrict__ FChi, const __half* __restrict__ FClos,
             const float* __restrict__ fcb, float* __restrict__ outp)
{
    extern __shared__ char smem_raw[];
    const uint32_t sb  = (smem_u32(smem_raw) + 1023u) & ~1023u;
    const int tid = threadIdx.x;
    const int wid = tid >> 5, lane = tid & 31;
    const int g = lane >> 2, t4 = lane & 3;
    const size_t SLOT = (size_t)BATCHN * HID;

    if (blockIdx.x < NCTA) {
        // =================== RNN path (round-12 verbatim) ===================
        const uint32_t PIN = sb;                 // 16 x 8KB pinned Whi
        const uint32_t STG = sb + 131072;        // 3 x 32KB stages
        const int wm  = wid >> 2, wn = wid & 3;
        const int grp = blockIdx.x >> 4;
        const size_t m0 = (size_t)grp * 32;
        const int    n0 = (blockIdx.x & 15) * 64;

        {
            const int r = tid >> 3, cc = tid & 7;
#pragma unroll 1
            for (int k0 = 0; k0 < 16; k0++) {
#pragma unroll
                for (int p = 0; p < 2; p++) {
                    int rr = r + p * 32;
                    CP_ASYNC16(PIN + k0 * 8192 + swz((uint32_t)(rr * 128 + cc * 16)),
                               Whi + (size_t)(n0 + rr) * HID + k0 * 64 + cc * 8);
                }
            }
            CP_COMMIT(); CP_WAIT0();
        }
        __syncthreads();

        float2 bb[2];
#pragma unroll
        for (int nf = 0; nf < 2; nf++) {
            int n = n0 + wn * 16 + nf * 8 + t4 * 2;
            bb[nf].x = bias[n]; bb[nf].y = bias[n + 1];
        }

        rnn_load_W2(STG, tid, 0, Wlos, n0);

#pragma unroll 1
        for (int t = 1; t < SEQ; t++) {
            if (t > 1) {
                if (tid == 0) poll_group(&g_bar[(t - 1) * 8 + grp], 32);
                __syncthreads();
            }

            const __half* Ahi = hhi  + (size_t)(t - 1) * SLOT;
            const __half* Alo = hlos + (size_t)(t - 1) * SLOT;
            rnn_load_A2(STG, tid, 0, Ahi, Alo, m0);
            rnn_load_full2(STG, tid, 1, Ahi, Alo, Wlos, m0, n0);

            float    acc0[2][4];
            uint32_t ach1[2][2], ach2[2][2];
#pragma unroll
            for (int j = 0; j < 2; j++) {
#pragma unroll
                for (int q = 0; q < 4; q++) acc0[j][q] = 0.f;
                ach1[j][0] = 0u; ach1[j][1] = 0u;
                ach2[j][0] = 0u; ach2[j][1] = 0u;
            }

#pragma unroll 1
            for (int k = 0; k < 8; k++) {
                if (k < 7) CP_WAIT1(); else CP_WAIT0();
                __syncthreads();
                if (k + 2 < 8)
                    rnn_load_full2(STG, tid, k + 2, Ahi, Alo, Wlos, m0, n0);
                const uint32_t stg0 = STG + (uint32_t)(k % 3) * 32768;
#pragma unroll
                for (int sub = 0; sub < 2; sub++) {
                    const uint32_t stg  = stg0 + (uint32_t)sub * 16384;
                    const uint32_t pinc = PIN + (uint32_t)(k * 2 + sub) * 8192;
#pragma unroll
                    for (int kk = 0; kk < 4; kk++) {
                        uint32_t afh[4], afl[4], bfh[4], bfl[4];
                        {
                            const int r0 = wm * 16 + (lane & 15);
                            const int c2 = (kk * 16 + (lane >> 4) * 8) * 2;
                            const uint32_t off = swz((uint32_t)(r0 * 128 + c2));
                            LDSM4(afh, stg + off);
                            LDSM4(afl, stg + 4096 + off);
                        }
                        {
                            const int r0 = wn * 16 + (lane & 7) + ((lane >> 4) << 3);
                            const int c2 = (kk * 16 + ((lane >> 3) & 1) * 8) * 2;
                            const uint32_t off = swz((uint32_t)(r0 * 128 + c2));
                            LDSM4(bfh, pinc + off);
                            LDSM4(bfl, stg + 8192 + off);
                        }
                        MMA16816(acc0[0], afh, bfh[0], bfh[1]);   // hi*hi
                        MMA16816(acc0[1], afh, bfh[2], bfh[3]);
                        MMA16816H(ach1[0], afh, bfl[0], bfl[1]);  // hi*wlo
                        MMA16816H(ach1[1], afh, bfl[2], bfl[3]);
                        MMA16816H(ach2[0], afl, bfh[0], bfh[1]);  // lo*whi
                        MMA16816H(ach2[1], afl, bfh[2], bfh[3]);
                    }
                }
            }

            // W prefetch chunk 0 of next step (slot 0 freed at iter-7 sync)
            if (t + 1 < SEQ)
                rnn_load_W2(STG, tid, 0, Wlos, n0);

            const size_t mr0 = m0 + wm * 16 + g;
            const int xr0 = x[mr0 * SEQ + t];
            const int xr1 = x[(mr0 + 8) * SEQ + t];
            const float* Pr[2] = { P + (size_t)xr0 * HID, P + (size_t)xr1 * HID };
            __half* dhi = hhi  + (size_t)t * SLOT;
            __half* dlo = hlos + (size_t)t * SLOT;
            float* hid = outp + (size_t)BATCHN * SEQ * VOCABN;
#pragma unroll
            for (int nf = 0; nf < 2; nf++) {
                const int n = n0 + wn * 16 + nf * 8 + t4 * 2;
#pragma unroll
                for (int h2 = 0; h2 < 2; h2++) {
                    const size_t m = mr0 + h2 * 8;
                    const __half2 c1 = *reinterpret_cast<const __half2*>(&ach1[nf][h2]);
                    const __half2 c2 = *reinterpret_cast<const __half2*>(&ach2[nf][h2]);
                    float v0 = acc0[nf][h2 * 2] +
                               0.03125f * (__low2float(c1)  + __low2float(c2)) +
                               bb[nf].x + Pr[h2][n];
                    float v1 = acc0[nf][h2 * 2 + 1] +
                               0.03125f * (__high2float(c1) + __high2float(c2)) +
                               bb[nf].y + Pr[h2][n + 1];
                    const float h0 = tanhf(v0), h1 = tanhf(v1);
                    const __half a0 = __float2half_rn(h0), a1 = __float2half_rn(h1);
                    const float f0 = __half2float(a0), f1 = __half2float(a1);
                    *(__half2*)(dhi + m * HID + n) = __halves2half2(a0, a1);
                    *(__half2*)(dlo + m * HID + n) =
                        __halves2half2(__float2half_rn((h0 - f0) * 32.f),
                                       __float2half_rn((h1 - f1) * 32.f));
                    if (t == SEQ - 1) {
                        float2 o; o.x = h0; o.y = h1;
                        *(float2*)(hid + m * HID + n) = o;
                    }
                }
            }

            __threadfence();
            __syncthreads();
            if (tid == 0)
                asm volatile("red.release.gpu.global.add.u32 [%0], %1;"
                             :: "l"(&g_bar[t * 8 + grp]), "r"(1u) : "memory");
        }

        // ========== tail: fc sliver for t in [TFC, SEQ) ==========
        // CTA -> (tt = TFC + bx>>3, rows [ (bx&7)*32, +32 )); M=32, N=128.
        {
            const int tt   = TFC + (blockIdx.x >> 3);
            const int mg   = blockIdx.x & 7;
            const int mrow = mg * 32;
            if (tid == 0) poll_group(&g_bar[tt * 8 + mg], 64);
            __syncthreads();                     // also fences smem reuse

            const __half* Ah = hhi  + (size_t)tt * SLOT + (size_t)mrow * HID;
            const __half* Al = hlos + (size_t)tt * SLOT + (size_t)mrow * HID;
            const uint32_t FST = sb;             // 4 stages x 20KB (reuse)
            const int twm = wid >> 2, twn = wid & 3;   // warp tile 16 x 32

            tail_load(FST, tid, 0, 0, Ah, Al, FChi, FClos);
            tail_load(FST, tid, 1, 1, Ah, Al, FChi, FClos);
            tail_load(FST, tid, 2, 2, Ah, Al, FChi, FClos);

            float    accA[4][4];
            uint32_t accBh[4][2];
#pragma unroll
            for (int j = 0; j < 4; j++) {
#pragma unroll
                for (int q = 0; q < 4; q++) accA[j][q] = 0.f;
                accBh[j][0] = 0u; accBh[j][1] = 0u;
            }

#pragma unroll 1
            for (int c = 0; c < 48; c++) {
                if (c < 46)       CP_WAIT2();
                else if (c == 46) CP_WAIT1();
                else              CP_WAIT0();
                __syncthreads();
                if (c + 3 < 48)
                    tail_load(FST, tid, (c + 3) & 3, c + 3, Ah, Al, FChi, FClos);

                const uint32_t stg = FST + (uint32_t)(c & 3) * 20480;
                const bool mainseg = (c >> 4) == 0;
#pragma unroll
                for (int kk = 0; kk < 4; kk++) {
                    uint32_t af[4], bf[2][4];
                    {
                        const int r0 = twm * 16 + (lane & 15);
                        const int c2 = (kk * 16 + (lane >> 4) * 8) * 2;
                        LDSM4(af, stg + swz((uint32_t)(r0 * 128 + c2)));
                    }
                    {
                        const int r0 = twn * 32 + (lane & 7) + ((lane >> 4) << 3);
                        const int c2 = (kk * 16 + ((lane >> 3) & 1) * 8) * 2;
#pragma unroll
                        for (int np = 0; np < 2; np++)
                            LDSM4(bf[np], stg + 4096 +
                                          swz((uint32_t)((r0 + np * 16) * 128 + c2)));
                    }
                    if (mainseg) {
#pragma unroll
                        for (int np = 0; np < 2; np++) {
                            MMA16816(accA[np * 2],     af, bf[np][0], bf[np][1]);
                            MMA16816(accA[np * 2 + 1], af, bf[np][2], bf[np][3]);
                        }
                    } else {
#pragma unroll
                        for (int np = 0; np < 2; np++) {
                            MMA16816H(accBh[np * 2],     af, bf[np][0], bf[np][1]);
                            MMA16816H(accBh[np * 2 + 1], af, bf[np][2], bf[np][3]);
                        }
                    }
                }
            }

#pragma unroll
            for (int nf = 0; nf < 4; nf++) {
                const int n = twn * 32 + (nf >> 1) * 16 + (nf & 1) * 8 + t4 * 2;
                const float b0 = fcb[n], b1 = fcb[n + 1];
#pragma unroll
                for (int h2 = 0; h2 < 2; h2++) {
                    const int mloc = twm * 16 + g + h2 * 8;
                    const size_t b = (size_t)mrow + mloc;
                    const __half2 cb =
                        *reinterpret_cast<const __half2*>(&accBh[nf][h2]);
                    float2 o;
                    o.x = accA[nf][h2 * 2]     + 0.03125f * __low2float(cb)  + b0;
                    o.y = accA[nf][h2 * 2 + 1] + 0.03125f * __high2float(cb) + b1;
                    *(float2*)(outp + (b * SEQ + tt) * VOCABN + n) = o;
                }
            }
        }
        return;
    }

    // ======================= fc consumer path (t < TFC, half units) ========
    const int cta = blockIdx.x - NCTA;
    const uint32_t FST = sb;                       // 4 stages x 32KB
    const int wm = wid >> 1, wn = wid & 1;
    const int gg = lane >> 2;

#pragma unroll 1
    for (int u = cta; u < 2 * TFC; u += NFC) {
        const int t = u >> 1, bh = u & 1;

        if (t >= 1) {                              // t=0 ready pre-launch
            if (tid < 4) poll_group(&g_bar[t * 8 + bh * 4 + tid], 128);
        }
        __syncthreads();

        const __half* Ah = hhi  + (size_t)t * SLOT + (size_t)bh * 128 * HID;
        const __half* Al = hlos + (size_t)t * SLOT + (size_t)bh * 128 * HID;

        fc_load(FST, tid, 0, 0, Ah, Al, FChi, FClos);
        fc_load(FST, tid, 1, 1, Ah, Al, FChi, FClos);
        fc_load(FST, tid, 2, 2, Ah, Al, FChi, FClos);

        float    accA[2][8][4];
        uint32_t accBh[2][8][2];
#pragma unroll
        for (int i = 0; i < 2; i++)
#pragma unroll
            for (int j = 0; j < 8; j++) {
#pragma unroll
                for (int q = 0; q < 4; q++) accA[i][j][q] = 0.f;
                accBh[i][j][0] = 0u; accBh[i][j][1] = 0u;
            }

#pragma unroll 1
        for (int c = 0; c < 48; c++) {
            if (c < 46)       CP_WAIT2();
            else if (c == 46) CP_WAIT1();
            else              CP_WAIT0();
            __syncthreads();
            if (c + 3 < 48)
                fc_load(FST, tid, (c + 3) & 3, c + 3, Ah, Al, FChi, FClos);

            const uint32_t stg = FST + (uint32_t)(c & 3) * 32768;
            const bool mainseg = (c >> 4) == 0;
#pragma unroll
            for (int kk = 0; kk < 4; kk++) {
                uint32_t af[2][4], bf[4][4];
                {
                    const int r0 = wm * 32 + (lane & 15);
                    const int c2 = (kk * 16 + (lane >> 4) * 8) * 2;
#pragma unroll
                    for (int mf = 0; mf < 2; mf++)
                        LDSM4(af[mf], stg + swz((uint32_t)((r0 + mf * 16) * 128 + c2)));
                }
                {
                    const int r0 = wn * 64 + (lane & 7) + ((lane >> 4) << 3);
                    const int c2 = (kk * 16 + ((lane >> 3) & 1) * 8) * 2;
#pragma unroll
                    for (int np = 0; np < 4; np++)
                        LDSM4(bf[np], stg + 16384 +
                                      swz((uint32_t)((r0 + np * 16) * 128 + c2)));
                }
                if (mainseg) {
#pragma unroll
                    for (int mf = 0; mf < 2; mf++)
#pragma unroll
                        for (int np = 0; np < 4; np++) {
                            MMA16816(accA[mf][np * 2],     af[mf], bf[np][0], bf[np][1]);
                            MMA16816(accA[mf][np * 2 + 1], af[mf], bf[np][2], bf[np][3]);
                        }
                } else {
#pragma unroll
                    for (int mf = 0; mf < 2; mf++)
#pragma unroll
                        for (int np = 0; np < 4; np++) {
                            MMA16816H(accBh[mf][np * 2],     af[mf], bf[np][0], bf[np][1]);
                            MMA16816H(accBh[mf][np * 2 + 1], af[mf], bf[np][2], bf[np][3]);
                        }
                }
            }
        }

#pragma unroll
        for (int mf = 0; mf < 2; mf++) {
#pragma unroll
            for (int nf = 0; nf < 8; nf++) {
                const int n = wn * 64 + (nf >> 1) * 16 + (nf & 1) * 8 + t4 * 2;
                const float b0 = fcb[n], b1 = fcb[n + 1];
#pragma unroll
                for (int h2 = 0; h2 < 2; h2++) {
                    const int mloc = wm * 32 + mf * 16 + gg + h2 * 8;
                    const size_t b = (size_t)bh * 128 + mloc;
                    const __half2 cb =
                        *reinterpret_cast<const __half2*>(&accBh[mf][nf][h2]);
                    float2 o;
                    o.x = accA[mf][nf][h2 * 2]     + 0.03125f * __low2float(cb)  + b0;
                    o.y = accA[mf][nf][h2 * 2 + 1] + 0.03125f * __high2float(cb) + b1;
                    *(float2*)(outp + (b * SEQ + t) * VOCABN + n) = o;
                }
            }
        }
        __syncthreads();
    }
}

// ===========================================================================
// Generic streaming 3-split GEMM (P precompute only) — unchanged.
// ===========================================================================
__device__ __forceinline__ void wait_chunk(int k0) {
    if (k0 < 14)       CP_WAIT2();
    else if (k0 == 14) CP_WAIT1();
    else               CP_WAIT0();
}

template<int BM, int BN>
__device__ __forceinline__ void g3_load(
    uint32_t STG, int tid, int k0, size_t m0, int n0,
    const __half* __restrict__ Ahi, const __half* __restrict__ Alos,
    const __half* __restrict__ Bhi, const __half* __restrict__ Blos)
{
    constexpr int STAGE = (2 * BM + 2 * BN) * 128;
    const uint32_t stg = STG + (uint32_t)(k0 & 3) * STAGE;
#pragma unroll
    for (int i = 0; i < BM * 8 / 256; i++) {
        int id = tid + i * 256, r = id >> 3, cc = id & 7;
        int kb = k0 * 64 + cc * 8;
        uint32_t off = swz((uint32_t)(r * 128 + cc * 16));
        CP_ASYNC16(stg + off,            Ahi  + (m0 + r) * (size_t)HID + kb);
        CP_ASYNC16(stg + BM * 128 + off, Alos + (m0 + r) * (size_t)HID + kb);
    }
#pragma unroll
    for (int i = 0; i < BN * 8 / 256; i++) {
        int id = tid + i * 256, r = id >> 3, cc = id & 7;
        int kb = k0 * 64 + cc * 8;
        uint32_t off = swz((uint32_t)(r * 128 + cc * 16));
        CP_ASYNC16(stg + 2 * BM * 128 + off,            Bhi  + (size_t)(n0 + r) * HID + kb);
        CP_ASYNC16(stg + 2 * BM * 128 + BN * 128 + off, Blos + (size_t)(n0 + r) * HID + kb);
    }
    CP_COMMIT();
}

template<int BM, int BN, int WM, int WN>
__global__ __launch_bounds__(256, 1)
void k_g3(const __half* __restrict__ Ahi, const __half* __restrict__ Alos,
          const __half* __restrict__ Bhi, const __half* __restrict__ Blos,
          const float* __restrict__ bias, float* __restrict__ Cf)
{
    constexpr int TM = BM / WM, TN = BN / WN;
    constexpr int MF = TM / 16, NF2 = TN / 16;
    constexpr int STAGE = (2 * BM + 2 * BN) * 128;

    extern __shared__ char smem_raw[];
    const uint32_t sb = (smem_u32(smem_raw) + 1023u) & ~1023u;
    const int tid = threadIdx.x, wid = tid >> 5, lane = tid & 31;
    const int wm = wid / WN, wn = wid % WN;
    const int n0 = blockIdx.x * BN;
    const size_t m0 = (size_t)blockIdx.y * BM;

    float acc[3][MF][NF2 * 2][4];
#pragma unroll
    for (int s = 0; s < 3; s++)
#pragma unroll
        for (int i = 0; i < MF; i++)
#pragma unroll
            for (int j = 0; j < NF2 * 2; j++)
#pragma unroll
                for (int q = 0; q < 4; q++) acc[s][i][j][q] = 0.f;

    g3_load<BM, BN>(sb, tid, 0, m0, n0, Ahi, Alos, Bhi, Blos);
    g3_load<BM, BN>(sb, tid, 1, m0, n0, Ahi, Alos, Bhi, Blos);
    g3_load<BM, BN>(sb, tid, 2, m0, n0, Ahi, Alos, Bhi, Blos);

#pragma unroll 1
    for (int k0 = 0; k0 < 16; k0++) {
        wait_chunk(k0);
        __syncthreads();
        if (k0 + 3 < 16)
            g3_load<BM, BN>(sb, tid, k0 + 3, m0, n0, Ahi, Alos, Bhi, Blos);
        const uint32_t stg = sb + (uint32_t)(k0 & 3) * STAGE;
        const uint32_t aH = stg, aL = stg + BM * 128;
        const uint32_t bH = stg + 2 * BM * 128, bL = bH + BN * 128;
#pragma unroll
        for (int kk = 0; kk < 4; kk++) {
            uint32_t afh[MF][4], afl[MF][4], bfh[NF2][4], bfl[NF2][4];
            {
                const int r0 = wm * TM + (lane & 15);
                const int c2 = (kk * 16 + (lane >> 4) * 8) * 2;
#pragma unroll
                for (int mf = 0; mf < MF; mf++) {
                    uint32_t off = swz((uint32_t)((r0 + mf * 16) * 128 + c2));
                    LDSM4(afh[mf], aH + off);
                    LDSM4(afl[mf], aL + off);
                }
            }
            {
                const int r0 = wn * TN + (lane & 7) + ((lane >> 4) << 3);
                const int c2 = (kk * 16 + ((lane >> 3) & 1) * 8) * 2;
#pragma unroll
                for (int np = 0; np < NF2; np++) {
                    uint32_t off = swz((uint32_t)((r0 + np * 16) * 128 + c2));
                    LDSM4(bfh[np], bH + off);
                    LDSM4(bfl[np], bL + off);
                }
            }
#pragma unroll
            for (int mf = 0; mf < MF; mf++)
#pragma unroll
                for (int np = 0; np < NF2; np++) {
                    MMA16816(acc[0][mf][np * 2],     afh[mf], bfh[np][0], bfh[np][1]);
                    MMA16816(acc[0][mf][np * 2 + 1], afh[mf], bfh[np][2], bfh[np][3]);
                    MMA16816(acc[1][mf][np * 2],     afh[mf], bfl[np][0], bfl[np][1]);
                    MMA16816(acc[1][mf][np * 2 + 1], afh[mf], bfl[np][2], bfl[np][3]);
                    MMA16816(acc[2][mf][np * 2],     afl[mf], bfh[np][0], bfh[np][1]);
                    MMA16816(acc[2][mf][np * 2 + 1], afl[mf], bfh[np][2], bfh[np][3]);
                }
        }
    }

    const int g = lane >> 2, t4 = lane & 3;
#pragma unroll
    for (int mf = 0; mf < MF; mf++) {
#pragma unroll
        for (int nf = 0; nf < NF2 * 2; nf++) {
            const int n = n0 + wn * TN + (nf >> 1) * 16 + (nf & 1) * 8 + t4 * 2;
            const float b0 = bias[n], b1 = bias[n + 1];
#pragma unroll
            for (int h2 = 0; h2 < 2; h2++) {
                const size_t m = m0 + wm * TM + mf * 16 + g + h2 * 8;
                float2 o;
                o.x = acc[0][mf][nf][h2 * 2] +
                      0.03125f * (acc[1][mf][nf][h2 * 2] + acc[2][mf][nf][h2 * 2]) + b0;
                o.y = acc[0][mf][nf][h2 * 2 + 1] +
                      0.03125f * (acc[1][mf][nf][h2 * 2 + 1] + acc[2][mf][nf][h2 * 2 + 1]) + b1;
                *(float2*)(Cf + m * HID + n) = o;
            }
        }
    }
}

// ---------------- small kernels ----------------
// merged split + barrier reset
__global__ __launch_bounds__(256)
void k_split_all(const float* __restrict__ whh, __half* __restrict__ whhhi,
                 __half* __restrict__ whhlos,
                 const float* __restrict__ wxh, __half* __restrict__ wxhhi,
                 __half* __restrict__ wxhlos,
                 const float* __restrict__ fcw, __half* __restrict__ fchi,
                 __half* __restrict__ fclos,
                 const float* __restrict__ emb, __half* __restrict__ embhi,
                 __half* __restrict__ emblos)
{
    int i = blockIdx.x * 256 + threadIdx.x;
    if (i < SEQ * 8) g_bar[i] = 0;
    {
        float v = whh[i];
        __half h = __float2half_rn(v);
        whhhi[i]  = h;
        whhlos[i] = __float2half_rn((v - __half2float(h)) * 32.f);
    }
    {
        float v = wxh[i];
        __half h = __float2half_rn(v);
        wxhhi[i]  = h;
        wxhlos[i] = __float2half_rn((v - __half2float(h)) * 32.f);
    }
    if (i < VOCABN * HID) {
        {
            float v = fcw[i];
            __half h = __float2half_rn(v);
            fchi[i]  = h;
            fclos[i] = __float2half_rn((v - __half2float(h)) * 32.f);
        }
        {
            float v = emb[i];
            __half h = __float2half_rn(v);
            embhi[i]  = h;
            emblos[i] = __float2half_rn((v - __half2float(h)) * 32.f);
        }
    }
}

__global__ __launch_bounds__(256)
void k_step0(const int* __restrict__ x, const float* __restrict__ P,
             const float* __restrict__ bias, __half* __restrict__ hhi,
             __half* __restrict__ hlos)
{
    int idx = blockIdx.x * 256 + threadIdx.x;
    int b = idx >> 10, n = idx & (HID - 1);
    float h = tanhf(P[(size_t)x[b * SEQ] * HID + n] + bias[n]);
    __half a = __float2half_rn(h);
    hhi[idx]  = a;
    hlos[idx] = __float2half_rn((h - __half2float(a)) * 32.f);
}

extern "C" void kernel_launch(void* const* d_in, const int* in_sizes, int n_in,
                              void* d_out, int out_size)
{
    const int*   x     = (const int*)  d_in[0];
    const float* embed = (const float*)d_in[1];
    const float* Wxh_w = (const float*)d_in[2];
    const float* Wxh_b = (const float*)d_in[3];
    const float* Whh_w = (const float*)d_in[4];
    const float* Whh_b = (const float*)d_in[5];
    const float* fc_w  = (const float*)d_in[6];
    const float* fc_b  = (const float*)d_in[7];
    float* outp = (float*)d_out;

    float* P;
    __half *hhi, *hlos, *whhhi, *whhlos, *wxhhi, *wxhlos, *embhi, *emblos, *fchi, *fclos;
    cudaGetSymbolAddress((void**)&P,      g_P);
    cudaGetSymbolAddress((void**)&hhi,    g_hhi);
    cudaGetSymbolAddress((void**)&hlos,   g_hlos);
    cudaGetSymbolAddress((void**)&whhhi,  g_whhhi);
    cudaGetSymbolAddress((void**)&whhlos, g_whhlos);
    cudaGetSymbolAddress((void**)&wxhhi,  g_wxhhi);
    cudaGetSymbolAddress((void**)&wxhlos, g_wxhlos);
    cudaGetSymbolAddress((void**)&embhi,  g_embhi);
    cudaGetSymbolAddress((void**)&emblos, g_emblos);
    cudaGetSymbolAddress((void**)&fchi,   g_fchi);
    cudaGetSymbolAddress((void**)&fclos,  g_fclos);

    const int SM_P   = (2 * 32 + 2 * 64) * 128 * 4 + 1024;    //  97 KB
    const int SM_RNN = 131072 + 3 * 32768 + 1024;             // 225 KB
    cudaFuncSetAttribute(k_g3<32, 64, 2, 4>,
                         cudaFuncAttributeMaxDynamicSharedMemorySize, SM_P);
    cudaFuncSetAttribute(k_fused,
                         cudaFuncAttributeMaxDynamicSharedMemorySize, SM_RNN);

    // 0) operand splits + barrier reset (single kernel)
    k_split_all<<<(HID * HID) / 256, 256>>>(Whh_w, whhhi, whhlos,
                                            Wxh_w, wxhhi, wxhlos,
                                            fc_w, fchi, fclos,
                                            embed, embhi, emblos);

    // 1) P = embed @ Wxh^T + bxh
    k_g3<32, 64, 2, 4><<<dim3(HID / 64, VOCABN / 32), 256, SM_P>>>(
        embhi, emblos, wxhhi, wxhlos, Wxh_b, P);

    // 2) t = 0
    k_step0<<<(BATCHN * HID) / 256, 256>>>(x, P, Whh_b, hhi, hlos);

    // 3) fused persistent: recurrence + tail fc + fc consumers
    k_fused<<<NCTA + NFC, 256, SM_RNN>>>(whhhi, whhlos, Whh_b, P, x, hhi, hlos,
                                         fchi, fclos, fc_b, outp);
}

// round 16
// speedup vs baseline: 1.0551x; 1.0143x over previous
#include <cuda_runtime.h>
#include <cuda_fp16.h>
#include <math.h>
#include <stdint.h>

#define VOCABN 128
#define HID    1024
#define BATCHN 256
#define SEQ    256
#define NCTA   128     // recurrence CTAs
#define NFC    20      // fc consumer CTAs
#define GRPSZ  16u
#define TFC    240     // fc consumers cover t < TFC; rnn CTAs cover the rest

// ---------------- device scratch (no allocations allowed) ----------------
__device__ float    g_P[VOCABN * HID];
__device__ __half   g_hhi [(size_t)SEQ * BATCHN * HID];
__device__ __half   g_hlos[(size_t)SEQ * BATCHN * HID];
__device__ __half   g_whhhi[HID * HID], g_whhlos[HID * HID];
__device__ __half   g_wxhhi[HID * HID], g_wxhlos[HID * HID];
__device__ __half   g_embhi[VOCABN * HID], g_emblos[VOCABN * HID];
__device__ __half   g_fchi[VOCABN * HID],  g_fclos[VOCABN * HID];
__device__ unsigned g_bar[SEQ * 8];                  // per-(step, m-group) counters

// ---------------- PTX helpers ----------------
__device__ __forceinline__ uint32_t smem_u32(const void* p) {
    uint32_t a;
    asm("{ .reg .u64 t; cvta.to.shared.u64 t, %1; cvt.u32.u64 %0, t; }" : "=r"(a) : "l"(p));
    return a;
}
__device__ __forceinline__ uint32_t swz(uint32_t o) { return o ^ ((o >> 3) & 0x70); }

// fast tanh: exp-based, abs err ~1e-6 (tanh.approx.f32 would be ~5e-4: too coarse)
__device__ __forceinline__ float ftanh(float x) {
    float xc = fminf(fmaxf(x, -9.f), 9.f);
    float e  = __expf(xc + xc);
    return __fdividef(e - 1.f, e + 1.f);
}

#define CP_ASYNC16(dst, src) \
    asm volatile("cp.async.cg.shared.global [%0], [%1], 16;" :: "r"(dst), "l"(src) : "memory")
#define CP_COMMIT() asm volatile("cp.async.commit_group;" ::: "memory")
#define CP_WAIT2()  asm volatile("cp.async.wait_group 2;" ::: "memory")
#define CP_WAIT1()  asm volatile("cp.async.wait_group 1;" ::: "memory")
#define CP_WAIT0()  asm volatile("cp.async.wait_group 0;" ::: "memory")

#define LDSM4(r, addr)                                                            \
    asm volatile("ldmatrix.sync.aligned.m8n8.x4.shared.b16 {%0,%1,%2,%3}, [%4];"  \
        : "=r"((r)[0]), "=r"((r)[1]), "=r"((r)[2]), "=r"((r)[3]) : "r"(addr))

// fp32-accumulate mma (main term — exact)
#define MMA16816(c, a, b0, b1)                                                    \
    asm volatile("mma.sync.aligned.m16n8k16.row.col.f32.f16.f16.f32 "             \
        "{%0,%1,%2,%3},{%4,%5,%6,%7},{%8,%9},{%0,%1,%2,%3};"                      \
        : "+f"((c)[0]), "+f"((c)[1]), "+f"((c)[2]), "+f"((c)[3])                   \
        : "r"((a)[0]), "r"((a)[1]), "r"((a)[2]), "r"((a)[3]), "r"(b0), "r"(b1))

// fp16-accumulate mma (correction terms)
#define MMA16816H(c, a, b0, b1)                                                   \
    asm volatile("mma.sync.aligned.m16n8k16.row.col.f16.f16.f16.f16 "             \
        "{%0,%1},{%2,%3,%4,%5},{%6,%7},{%0,%1};"                                  \
        : "+r"((c)[0]), "+r"((c)[1])                                              \
        : "r"((a)[0]), "r"((a)[1]), "r"((a)[2]), "r"((a)[3]), "r"(b0), "r"(b1))

__device__ __forceinline__ void poll_group(const unsigned* slot, int sleep_ns) {
    unsigned v;
    while (true) {
        asm volatile("ld.acquire.gpu.global.u32 %0, [%1];"
                     : "=r"(v) : "l"(slot) : "memory");
        if (v >= GRPSZ) break;
        __nanosleep(sleep_ns);
    }
}

// ===========================================================================
// RNN loaders. Big chunk = K=128 = two 16KB halves, slot = bk % 3 (32KB each).
// Half layout: [Ahi fp16 4KB | Alo fp16 4KB | Wlos fp16 8KB], all SW128.
// ===========================================================================
__device__ __forceinline__ void rnn_load_W2(
    uint32_t STG, int tid, int bk, const __half* __restrict__ Wlos, int n0)
{
    const uint32_t stg0 = STG + (uint32_t)(bk % 3) * 32768;
    const int r = tid >> 3, cc = tid & 7;
#pragma unroll
    for (int sub = 0; sub < 2; sub++) {
        const int kb = (bk * 2 + sub) * 64 + cc * 8;
        const uint32_t stg = stg0 + (uint32_t)sub * 16384;
        CP_ASYNC16(stg + 8192 + swz((uint32_t)(r * 128 + cc * 16)),
                   Wlos + (size_t)(n0 + r) * HID + kb);
        CP_ASYNC16(stg + 8192 + swz((uint32_t)((r + 32) * 128 + cc * 16)),
                   Wlos + (size_t)(n0 + r + 32) * HID + kb);
    }
    CP_COMMIT();
}

__device__ __forceinline__ void rnn_load_A2(
    uint32_t STG, int tid, int bk,
    const __half* __restrict__ Ahi, const __half* __restrict__ Alo, size_t m0)
{
    const uint32_t stg0 = STG + (uint32_t)(bk % 3) * 32768;
    const int r = tid >> 3, cc = tid & 7;
    const uint32_t off = swz((uint32_t)(r * 128 + cc * 16));
#pragma unroll
    for (int sub = 0; sub < 2; sub++) {
        const int kb = (bk * 2 + sub) * 64 + cc * 8;
        const uint32_t stg = stg0 + (uint32_t)sub * 16384;
        CP_ASYNC16(stg + off,        Ahi + (m0 + r) * (size_t)HID + kb);
        CP_ASYNC16(stg + 4096 + off, Alo + (m0 + r) * (size_t)HID + kb);
    }
    CP_COMMIT();
}

__device__ __forceinline__ void rnn_load_full2(
    uint32_t STG, int tid, int bk,
    const __half* __restrict__ Ahi, const __half* __restrict__ Alo,
    const __half* __restrict__ Wlos, size_t m0, int n0)
{
    const uint32_t stg0 = STG + (uint32_t)(bk % 3) * 32768;
    const int r = tid >> 3, cc = tid & 7;
    const uint32_t off = swz((uint32_t)(r * 128 + cc * 16));
#pragma unroll
    for (int sub = 0; sub < 2; sub++) {
        const int kb = (bk * 2 + sub) * 64 + cc * 8;
        const uint32_t stg = stg0 + (uint32_t)sub * 16384;
        CP_ASYNC16(stg + off,        Ahi + (m0 + r) * (size_t)HID + kb);
        CP_ASYNC16(stg + 4096 + off, Alo + (m0 + r) * (size_t)HID + kb);
        CP_ASYNC16(stg + 8192 + off, Wlos + (size_t)(n0 + r) * HID + kb);
        CP_ASYNC16(stg + 8192 + swz((uint32_t)((r + 32) * 128 + cc * 16)),
                   Wlos + (size_t)(n0 + r + 32) * HID + kb);
    }
    CP_COMMIT();
}

// ---- fc consumer loader: half unit, A = 128 rows, B = 128 rows ----
__device__ __forceinline__ void fc_load(
    uint32_t FST, int tid, int slot, int c,
    const __half* __restrict__ Ahi, const __half* __restrict__ Alos,
    const __half* __restrict__ Bhi, const __half* __restrict__ Blos)
{
    const int seg = c >> 4;
    const __half* A = (seg == 2) ? Alos : Ahi;
    const __half* B = (seg == 1) ? Blos : Bhi;
    const uint32_t stg = FST + (uint32_t)slot * 32768;
#pragma unroll
    for (int i = 0; i < 4; i++) {
        int id = tid + i * 256, r = id >> 3;
        uint32_t off = swz((uint32_t)(r * 128 + (id & 7) * 16));
        CP_ASYNC16(stg + off, A + (size_t)r * HID + (c & 15) * 64 + (id & 7) * 8);
    }
#pragma unroll
    for (int i = 0; i < 4; i++) {
        int id = tid + i * 256, r = id >> 3;
        uint32_t off = swz((uint32_t)(r * 128 + (id & 7) * 16));
        CP_ASYNC16(stg + 16384 + off, B + (size_t)r * HID + (c & 15) * 64 + (id & 7) * 8);
    }
    CP_COMMIT();
}

// ---- tail fc loader: A = 32 rows, B = 128 rows. Stage 20KB x 4. ----
__device__ __forceinline__ void tail_load(
    uint32_t FST, int tid, int slot, int c,
    const __half* __restrict__ Ahi, const __half* __restrict__ Alos,
    const __half* __restrict__ Bhi, const __half* __restrict__ Blos)
{
    const int seg = c >> 4;
    const __half* A = (seg == 2) ? Alos : Ahi;
    const __half* B = (seg == 1) ? Blos : Bhi;
    const uint32_t stg = FST + (uint32_t)slot * 20480;
    {
        int r = tid >> 3;
        uint32_t off = swz((uint32_t)(r * 128 + (tid & 7) * 16));
        CP_ASYNC16(stg + off, A + (size_t)r * HID + (c & 15) * 64 + (tid & 7) * 8);
    }
#pragma unroll
    for (int i = 0; i < 4; i++) {
        int id = tid + i * 256, r = id >> 3;
        uint32_t off = swz((uint32_t)(r * 128 + (id & 7) * 16));
        CP_ASYNC16(stg + 4096 + off, B + (size_t)r * HID + (c & 15) * 64 + (id & 7) * 8);
    }
    CP_COMMIT();
}

// ===========================================================================
// Fused persistent kernel: CTAs 0..127 recurrence then a tail-fc sliver each;
// CTAs 128..147 fc consumers for t < TFC.
// ===========================================================================
__global__ __launch_bounds__(256, 1)
void k_fused(const __half* __restrict__ Whi, const __half* __restrict__ Wlos,
             const float* __restrict__ bias, const float* __restrict__ P,
             const int* __restrict__ x,
             __half* __restrict__ hhi, __half* __restrict__ hlos,
             const __half* __restrict__ FChi, const __half* __restrict__ FClos,
             const float* __restrict__ fcb, float* __restrict__ outp)
{
    extern __shared__ char smem_raw[];
    const uint32_t sb  = (smem_u32(smem_raw) + 1023u) & ~1023u;
    const int tid = threadIdx.x;
    const int wid = tid >> 5, lane = tid & 31;
    const int g = lane >> 2, t4 = lane & 3;
    const size_t SLOT = (size_t)BATCHN * HID;

    if (blockIdx.x < NCTA) {
        // =================== RNN path ===================
        const uint32_t PIN = sb;                 // 16 x 8KB pinned Whi
        const uint32_t STG = sb + 131072;        // 3 x 32KB stages
        const int wm  = wid >> 2, wn = wid & 3;
        const int grp = blockIdx.x >> 4;
        const size_t m0 = (size_t)grp * 32;
        const int    n0 = (blockIdx.x & 15) * 64;

        {
            const int r = tid >> 3, cc = tid & 7;
#pragma unroll 1
            for (int k0 = 0; k0 < 16; k0++) {
#pragma unroll
                for (int p = 0; p < 2; p++) {
                    int rr = r + p * 32;
                    CP_ASYNC16(PIN + k0 * 8192 + swz((uint32_t)(rr * 128 + cc * 16)),
                               Whi + (size_t)(n0 + rr) * HID + k0 * 64 + cc * 8);
                }
            }
            CP_COMMIT(); CP_WAIT0();
        }
        __syncthreads();

        float2 bb[2];
#pragma unroll
        for (int nf = 0; nf < 2; nf++) {
            int n = n0 + wn * 16 + nf * 8 + t4 * 2;
            bb[nf].x = bias[n]; bb[nf].y = bias[n + 1];
        }

        rnn_load_W2(STG, tid, 0, Wlos, n0);

        const size_t mr0 = m0 + wm * 16 + g;     // fixed epilogue rows

#pragma unroll 1
        for (int t = 1; t < SEQ; t++) {
            if (t > 1) {
                if (tid == 0) poll_group(&g_bar[(t - 1) * 8 + grp], 32);
                __syncthreads();
            }

            // ---- prefetch epilogue operands (P-gather hidden under MMA) ----
            const int xr0 = x[mr0 * SEQ + t];
            const int xr1 = x[(mr0 + 8) * SEQ + t];
            float2 pv[2][2];                     // [h2][nf]
#pragma unroll
            for (int nf = 0; nf < 2; nf++) {
                const int n = n0 + wn * 16 + nf * 8 + t4 * 2;
                pv[0][nf] = *(const float2*)(P + (size_t)xr0 * HID + n);
                pv[1][nf] = *(const float2*)(P + (size_t)xr1 * HID + n);
            }

            const __half* Ahi = hhi  + (size_t)(t - 1) * SLOT;
            const __half* Alo = hlos + (size_t)(t - 1) * SLOT;
            rnn_load_A2(STG, tid, 0, Ahi, Alo, m0);
            rnn_load_full2(STG, tid, 1, Ahi, Alo, Wlos, m0, n0);

            float    acc0[2][4];
            uint32_t ach1[2][2], ach2[2][2];
#pragma unroll
            for (int j = 0; j < 2; j++) {
#pragma unroll
                for (int q = 0; q < 4; q++) acc0[j][q] = 0.f;
                ach1[j][0] = 0u; ach1[j][1] = 0u;
                ach2[j][0] = 0u; ach2[j][1] = 0u;
            }

#pragma unroll 1
            for (int k = 0; k < 8; k++) {
                if (k < 7) CP_WAIT1(); else CP_WAIT0();
                __syncthreads();
                if (k + 2 < 8)
                    rnn_load_full2(STG, tid, k + 2, Ahi, Alo, Wlos, m0, n0);
                const uint32_t stg0 = STG + (uint32_t)(k % 3) * 32768;
#pragma unroll
                for (int sub = 0; sub < 2; sub++) {
                    const uint32_t stg  = stg0 + (uint32_t)sub * 16384;
                    const uint32_t pinc = PIN + (uint32_t)(k * 2 + sub) * 8192;
#pragma unroll
                    for (int kk = 0; kk < 4; kk++) {
                        uint32_t afh[4], afl[4], bfh[4], bfl[4];
                        {
                            const int r0 = wm * 16 + (lane & 15);
                            const int c2 = (kk * 16 + (lane >> 4) * 8) * 2;
                            const uint32_t off = swz((uint32_t)(r0 * 128 + c2));
                            LDSM4(afh, stg + off);
                            LDSM4(afl, stg + 4096 + off);
                        }
                        {
                            const int r0 = wn * 16 + (lane & 7) + ((lane >> 4) << 3);
                            const int c2 = (kk * 16 + ((lane >> 3) & 1) * 8) * 2;
                            const uint32_t off = swz((uint32_t)(r0 * 128 + c2));
                            LDSM4(bfh, pinc + off);
                            LDSM4(bfl, stg + 8192 + off);
                        }
                        MMA16816(acc0[0], afh, bfh[0], bfh[1]);   // hi*hi
                        MMA16816(acc0[1], afh, bfh[2], bfh[3]);
                        MMA16816H(ach1[0], afh, bfl[0], bfl[1]);  // hi*wlo
                        MMA16816H(ach1[1], afh, bfl[2], bfl[3]);
                        MMA16816H(ach2[0], afl, bfh[0], bfh[1]);  // lo*whi
                        MMA16816H(ach2[1], afl, bfh[2], bfh[3]);
                    }
                }
            }

            // W prefetch chunk 0 of next step (slot 0 freed at iter-7 sync)
            if (t + 1 < SEQ)
                rnn_load_W2(STG, tid, 0, Wlos, n0);

            __half* dhi = hhi  + (size_t)t * SLOT;
            __half* dlo = hlos + (size_t)t * SLOT;
            float* hid = outp + (size_t)BATCHN * SEQ * VOCABN;
#pragma unroll
            for (int nf = 0; nf < 2; nf++) {
                const int n = n0 + wn * 16 + nf * 8 + t4 * 2;
#pragma unroll
                for (int h2 = 0; h2 < 2; h2++) {
                    const size_t m = mr0 + h2 * 8;
                    const __half2 c1 = *reinterpret_cast<const __half2*>(&ach1[nf][h2]);
                    const __half2 c2 = *reinterpret_cast<const __half2*>(&ach2[nf][h2]);
                    float v0 = acc0[nf][h2 * 2] +
                               0.03125f * (__low2float(c1)  + __low2float(c2)) +
                               bb[nf].x + pv[h2][nf].x;
                    float v1 = acc0[nf][h2 * 2 + 1] +
                               0.03125f * (__high2float(c1) + __high2float(c2)) +
                               bb[nf].y + pv[h2][nf].y;
                    const float h0 = ftanh(v0), h1 = ftanh(v1);
                    const __half a0 = __float2half_rn(h0), a1 = __float2half_rn(h1);
                    const float f0 = __half2float(a0), f1 = __half2float(a1);
                    *(__half2*)(dhi + m * HID + n) = __halves2half2(a0, a1);
                    *(__half2*)(dlo + m * HID + n) =
                        __halves2half2(__float2half_rn((h0 - f0) * 32.f),
                                       __float2half_rn((h1 - f1) * 32.f));
                    if (t == SEQ - 1) {
                        float2 o; o.x = h0; o.y = h1;
                        *(float2*)(hid + m * HID + n) = o;
                    }
                }
            }

            __threadfence();
            __syncthreads();
            if (tid == 0)
                asm volatile("red.release.gpu.global.add.u32 [%0], %1;"
                             :: "l"(&g_bar[t * 8 + grp]), "r"(1u) : "memory");
        }

        // ========== tail: fc sliver for t in [TFC, SEQ) ==========
        {
            const int tt   = TFC + (blockIdx.x >> 3);
            const int mg   = blockIdx.x & 7;
            const int mrow = mg * 32;
            if (tid == 0) poll_group(&g_bar[tt * 8 + mg], 64);
            __syncthreads();

            const __half* Ah = hhi  + (size_t)tt * SLOT + (size_t)mrow * HID;
            const __half* Al = hlos + (size_t)tt * SLOT + (size_t)mrow * HID;
            const uint32_t FST = sb;
            const int twm = wid >> 2, twn = wid & 3;

            tail_load(FST, tid, 0, 0, Ah, Al, FChi, FClos);
            tail_load(FST, tid, 1, 1, Ah, Al, FChi, FClos);
            tail_load(FST, tid, 2, 2, Ah, Al, FChi, FClos);

            float    accA[4][4];
            uint32_t accBh[4][2];
#pragma unroll
            for (int j = 0; j < 4; j++) {
#pragma unroll
                for (int q = 0; q < 4; q++) accA[j][q] = 0.f;
                accBh[j][0] = 0u; accBh[j][1] = 0u;
            }

#pragma unroll 1
            for (int c = 0; c < 48; c++) {
                if (c < 46)       CP_WAIT2();
                else if (c == 46) CP_WAIT1();
                else              CP_WAIT0();
                __syncthreads();
                if (c + 3 < 48)
                    tail_load(FST, tid, (c + 3) & 3, c + 3, Ah, Al, FChi, FClos);

                const uint32_t stg = FST + (uint32_t)(c & 3) * 20480;
                const bool mainseg = (c >> 4) == 0;
#pragma unroll
                for (int kk = 0; kk < 4; kk++) {
                    uint32_t af[4], bf[2][4];
                    {
                        const int r0 = twm * 16 + (lane & 15);
                        const int c2 = (kk * 16 + (lane >> 4) * 8) * 2;
                        LDSM4(af, stg + swz((uint32_t)(r0 * 128 + c2)));
                    }
                    {
                        const int r0 = twn * 32 + (lane & 7) + ((lane >> 4) << 3);
                        const int c2 = (kk * 16 + ((lane >> 3) & 1) * 8) * 2;
#pragma unroll
                        for (int np = 0; np < 2; np++)
                            LDSM4(bf[np], stg + 4096 +
                                          swz((uint32_t)((r0 + np * 16) * 128 + c2)));
                    }
                    if (mainseg) {
#pragma unroll
                        for (int np = 0; np < 2; np++) {
                            MMA16816(accA[np * 2],     af, bf[np][0], bf[np][1]);
                            MMA16816(accA[np * 2 + 1], af, bf[np][2], bf[np][3]);
                        }
                    } else {
#pragma unroll
                        for (int np = 0; np < 2; np++) {
                            MMA16816H(accBh[np * 2],     af, bf[np][0], bf[np][1]);
                            MMA16816H(accBh[np * 2 + 1], af, bf[np][2], bf[np][3]);
                        }
                    }
                }
            }

#pragma unroll
            for (int nf = 0; nf < 4; nf++) {
                const int n = twn * 32 + (nf >> 1) * 16 + (nf & 1) * 8 + t4 * 2;
                const float b0 = fcb[n], b1 = fcb[n + 1];
#pragma unroll
                for (int h2 = 0; h2 < 2; h2++) {
                    const int mloc = twm * 16 + g + h2 * 8;
                    const size_t b = (size_t)mrow + mloc;
                    const __half2 cb =
                        *reinterpret_cast<const __half2*>(&accBh[nf][h2]);
                    float2 o;
                    o.x = accA[nf][h2 * 2]     + 0.03125f * __low2float(cb)  + b0;
                    o.y = accA[nf][h2 * 2 + 1] + 0.03125f * __high2float(cb) + b1;
                    *(float2*)(outp + (b * SEQ + tt) * VOCABN + n) = o;
                }
            }
        }
        return;
    }

    // ======================= fc consumer path (t < TFC, half units) ========
    const int cta = blockIdx.x - NCTA;
    const uint32_t FST = sb;
    const int wm = wid >> 1, wn = wid & 1;
    const int gg = lane >> 2;

#pragma unroll 1
    for (int u = cta; u < 2 * TFC; u += NFC) {
        const int t = u >> 1, bh = u & 1;

        if (t >= 1) {
            if (tid < 4) poll_group(&g_bar[t * 8 + bh * 4 + tid], 128);
        }
        __syncthreads();

        const __half* Ah = hhi  + (size_t)t * SLOT + (size_t)bh * 128 * HID;
        const __half* Al = hlos + (size_t)t * SLOT + (size_t)bh * 128 * HID;

        fc_load(FST, tid, 0, 0, Ah, Al, FChi, FClos);
        fc_load(FST, tid, 1, 1, Ah, Al, FChi, FClos);
        fc_load(FST, tid, 2, 2, Ah, Al, FChi, FClos);

        float    accA[2][8][4];
        uint32_t accBh[2][8][2];
#pragma unroll
        for (int i = 0; i < 2; i++)
#pragma unroll
            for (int j = 0; j < 8; j++) {
#pragma unroll
                for (int q = 0; q < 4; q++) accA[i][j][q] = 0.f;
                accBh[i][j][0] = 0u; accBh[i][j][1] = 0u;
            }

#pragma unroll 1
        for (int c = 0; c < 48; c++) {
            if (c < 46)       CP_WAIT2();
            else if (c == 46) CP_WAIT1();
            else              CP_WAIT0();
            __syncthreads();
            if (c + 3 < 48)
                fc_load(FST, tid, (c + 3) & 3, c + 3, Ah, Al, FChi, FClos);

            const uint32_t stg = FST + (uint32_t)(c & 3) * 32768;
            const bool mainseg = (c >> 4) == 0;
#pragma unroll
            for (int kk = 0; kk < 4; kk++) {
                uint32_t af[2][4], bf[4][4];
                {
                    const int r0 = wm * 32 + (lane & 15);
                    const int c2 = (kk * 16 + (lane >> 4) * 8) * 2;
#pragma unroll
                    for (int mf = 0; mf < 2; mf++)
                        LDSM4(af[mf], stg + swz((uint32_t)((r0 + mf * 16) * 128 + c2)));
                }
                {
                    const int r0 = wn * 64 + (lane & 7) + ((lane >> 4) << 3);
                    const int c2 = (kk * 16 + ((lane >> 3) & 1) * 8) * 2;
#pragma unroll
                    for (int np = 0; np < 4; np++)
                        LDSM4(bf[np], stg + 16384 +
                                      swz((uint32_t)((r0 + np * 16) * 128 + c2)));
                }
                if (mainseg) {
#pragma unroll
                    for (int mf = 0; mf < 2; mf++)
#pragma unroll
                        for (int np = 0; np < 4; np++) {
                            MMA16816(accA[mf][np * 2],     af[mf], bf[np][0], bf[np][1]);
                            MMA16816(accA[mf][np * 2 + 1], af[mf], bf[np][2], bf[np][3]);
                        }
                } else {
#pragma unroll
                    for (int mf = 0; mf < 2; mf++)
#pragma unroll
                        for (int np = 0; np < 4; np++) {
                            MMA16816H(accBh[mf][np * 2],     af[mf], bf[np][0], bf[np][1]);
                            MMA16816H(accBh[mf][np * 2 + 1], af[mf], bf[np][2], bf[np][3]);
                        }
                }
            }
        }

#pragma unroll
        for (int mf = 0; mf < 2; mf++) {
#pragma unroll
            for (int nf = 0; nf < 8; nf++) {
                const int n = wn * 64 + (nf >> 1) * 16 + (nf & 1) * 8 + t4 * 2;
                const float b0 = fcb[n], b1 = fcb[n + 1];
#pragma unroll
                for (int h2 = 0; h2 < 2; h2++) {
                    const int mloc = wm * 32 + mf * 16 + gg + h2 * 8;
                    const size_t b = (size_t)bh * 128 + mloc;
                    const __half2 cb =
                        *reinterpret_cast<const __half2*>(&accBh[mf][nf][h2]);
                    float2 o;
                    o.x = accA[mf][nf][h2 * 2]     + 0.03125f * __low2float(cb)  + b0;
                    o.y = accA[mf][nf][h2 * 2 + 1] + 0.03125f * __high2float(cb) + b1;
                    *(float2*)(outp + (b * SEQ + t) * VOCABN + n) = o;
                }
            }
        }
        __syncthreads();
    }
}

// ===========================================================================
// Generic streaming 3-split GEMM (P precompute only) — unchanged.
// ===========================================================================
__device__ __forceinline__ void wait_chunk(int k0) {
    if (k0 < 14)       CP_WAIT2();
    else if (k0 == 14) CP_WAIT1();
    else               CP_WAIT0();
}

template<int BM, int BN>
__device__ __forceinline__ void g3_load(
    uint32_t STG, int tid, int k0, size_t m0, int n0,
    const __half* __restrict__ Ahi, const __half* __restrict__ Alos,
    const __half* __restrict__ Bhi, const __half* __restrict__ Blos)
{
    constexpr int STAGE = (2 * BM + 2 * BN) * 128;
    const uint32_t stg = STG + (uint32_t)(k0 & 3) * STAGE;
#pragma unroll
    for (int i = 0; i < BM * 8 / 256; i++) {
        int id = tid + i * 256, r = id >> 3, cc = id & 7;
        int kb = k0 * 64 + cc * 8;
        uint32_t off = swz((uint32_t)(r * 128 + cc * 16));
        CP_ASYNC16(stg + off,            Ahi  + (m0 + r) * (size_t)HID + kb);
        CP_ASYNC16(stg + BM * 128 + off, Alos + (m0 + r) * (size_t)HID + kb);
    }
#pragma unroll
    for (int i = 0; i < BN * 8 / 256; i++) {
        int id = tid + i * 256, r = id >> 3, cc = id & 7;
        int kb = k0 * 64 + cc * 8;
        uint32_t off = swz((uint32_t)(r * 128 + cc * 16));
        CP_ASYNC16(stg + 2 * BM * 128 + off,            Bhi  + (size_t)(n0 + r) * HID + kb);
        CP_ASYNC16(stg + 2 * BM * 128 + BN * 128 + off, Blos + (size_t)(n0 + r) * HID + kb);
    }
    CP_COMMIT();
}

template<int BM, int BN, int WM, int WN>
__global__ __launch_bounds__(256, 1)
void k_g3(const __half* __restrict__ Ahi, const __half* __restrict__ Alos,
          const __half* __restrict__ Bhi, const __half* __restrict__ Blos,
          const float* __restrict__ bias, float* __restrict__ Cf)
{
    constexpr int TM = BM / WM, TN = BN / WN;
    constexpr int MF = TM / 16, NF2 = TN / 16;
    constexpr int STAGE = (2 * BM + 2 * BN) * 128;

    extern __shared__ char smem_raw[];
    const uint32_t sb = (smem_u32(smem_raw) + 1023u) & ~1023u;
    const int tid = threadIdx.x, wid = tid >> 5, lane = tid & 31;
    const int wm = wid / WN, wn = wid % WN;
    const int n0 = blockIdx.x * BN;
    const size_t m0 = (size_t)blockIdx.y * BM;

    float acc[3][MF][NF2 * 2][4];
#pragma unroll
    for (int s = 0; s < 3; s++)
#pragma unroll
        for (int i = 0; i < MF; i++)
#pragma unroll
            for (int j = 0; j < NF2 * 2; j++)
#pragma unroll
                for (int q = 0; q < 4; q++) acc[s][i][j][q] = 0.f;

    g3_load<BM, BN>(sb, tid, 0, m0, n0, Ahi, Alos, Bhi, Blos);
    g3_load<BM, BN>(sb, tid, 1, m0, n0, Ahi, Alos, Bhi, Blos);
    g3_load<BM, BN>(sb, tid, 2, m0, n0, Ahi, Alos, Bhi, Blos);

#pragma unroll 1
    for (int k0 = 0; k0 < 16; k0++) {
        wait_chunk(k0);
        __syncthreads();
        if (k0 + 3 < 16)
            g3_load<BM, BN>(sb, tid, k0 + 3, m0, n0, Ahi, Alos, Bhi, Blos);
        const uint32_t stg = sb + (uint32_t)(k0 & 3) * STAGE;
        const uint32_t aH = stg, aL = stg + BM * 128;
        const uint32_t bH = stg + 2 * BM * 128, bL = bH + BN * 128;
#pragma unroll
        for (int kk = 0; kk < 4; kk++) {
            uint32_t afh[MF][4], afl[MF][4], bfh[NF2][4], bfl[NF2][4];
            {
                const int r0 = wm * TM + (lane & 15);
                const int c2 = (kk * 16 + (lane >> 4) * 8) * 2;
#pragma unroll
                for (int mf = 0; mf < MF; mf++) {
                    uint32_t off = swz((uint32_t)((r0 + mf * 16) * 128 + c2));
                    LDSM4(afh[mf], aH + off);
                    LDSM4(afl[mf], aL + off);
                }
            }
            {
                const int r0 = wn * TN + (lane & 7) + ((lane >> 4) << 3);
                const int c2 = (kk * 16 + ((lane >> 3) & 1) * 8) * 2;
#pragma unroll
                for (int np = 0; np < NF2; np++) {
                    uint32_t off = swz((uint32_t)((r0 + np * 16) * 128 + c2));
                    LDSM4(bfh[np], bH + off);
                    LDSM4(bfl[np], bL + off);
                }
            }
#pragma unroll
            for (int mf = 0; mf < MF; mf++)
#pragma unroll
                for (int np = 0; np < NF2; np++) {
                    MMA16816(acc[0][mf][np * 2],     afh[mf], bfh[np][0], bfh[np][1]);
                    MMA16816(acc[0][mf][np * 2 + 1], afh[mf], bfh[np][2], bfh[np][3]);
                    MMA16816(acc[1][mf][np * 2],     afh[mf], bfl[np][0], bfl[np][1]);
                    MMA16816(acc[1][mf][np * 2 + 1], afh[mf], bfl[np][2], bfl[np][3]);
                    MMA16816(acc[2][mf][np * 2],     afl[mf], bfh[np][0], bfh[np][1]);
                    MMA16816(acc[2][mf][np * 2 + 1], afl[mf], bfh[np][2], bfh[np][3]);
                }
        }
    }

    const int g = lane >> 2, t4 = lane & 3;
#pragma unroll
    for (int mf = 0; mf < MF; mf++) {
#pragma unroll
        for (int nf = 0; nf < NF2 * 2; nf++) {
            const int n = n0 + wn * TN + (nf >> 1) * 16 + (nf & 1) * 8 + t4 * 2;
            const float b0 = bias[n], b1 = bias[n + 1];
#pragma unroll
            for (int h2 = 0; h2 < 2; h2++) {
                const size_t m = m0 + wm * TM + mf * 16 + g + h2 * 8;
                float2 o;
                o.x = acc[0][mf][nf][h2 * 2] +
                      0.03125f * (acc[1][mf][nf][h2 * 2] + acc[2][mf][nf][h2 * 2]) + b0;
                o.y = acc[0][mf][nf][h2 * 2 + 1] +
                      0.03125f * (acc[1][mf][nf][h2 * 2 + 1] + acc[2][mf][nf][h2 * 2 + 1]) + b1;
                *(float2*)(Cf + m * HID + n) = o;
            }
        }
    }
}

// ---------------- small kernels ----------------
__global__ __launch_bounds__(256)
void k_split_all(const float* __restrict__ whh, __half* __restrict__ whhhi,
                 __half* __restrict__ whhlos,
                 const float* __restrict__ wxh, __half* __restrict__ wxhhi,
                 __half* __restrict__ wxhlos,
                 const float* __restrict__ fcw, __half* __restrict__ fchi,
                 __half* __restrict__ fclos,
                 const float* __restrict__ emb, __half* __restrict__ embhi,
                 __half* __restrict__ emblos)
{
    int i = blockIdx.x * 256 + threadIdx.x;
    if (i < SEQ * 8) g_bar[i] = 0;
    {
        float v = whh[i];
        __half h = __float2half_rn(v);
        whhhi[i]  = h;
        whhlos[i] = __float2half_rn((v - __half2float(h)) * 32.f);
    }
    {
        float v = wxh[i];
        __half h = __float2half_rn(v);
        wxhhi[i]  = h;
        wxhlos[i] = __float2half_rn((v - __half2float(h)) * 32.f);
    }
    if (i < VOCABN * HID) {
        {
            float v = fcw[i];
            __half h = __float2half_rn(v);
            fchi[i]  = h;
            fclos[i] = __float2half_rn((v - __half2float(h)) * 32.f);
        }
        {
            float v = emb[i];
            __half h = __float2half_rn(v);
            embhi[i]  = h;
            emblos[i] = __float2half_rn((v - __half2float(h)) * 32.f);
        }
    }
}

__global__ __launch_bounds__(256)
void k_step0(const int* __restrict__ x, const float* __restrict__ P,
             const float* __restrict__ bias, __half* __restrict__ hhi,
             __half* __restrict__ hlos)
{
    int idx = blockIdx.x * 256 + threadIdx.x;
    int b = idx >> 10, n = idx & (HID - 1);
    float h = ftanh(P[(size_t)x[b * SEQ] * HID + n] + bias[n]);
    __half a = __float2half_rn(h);
    hhi[idx]  = a;
    hlos[idx] = __float2half_rn((h - __half2float(a)) * 32.f);
}

extern "C" void kernel_launch(void* const* d_in, const int* in_sizes, int n_in,
                              void* d_out, int out_size)
{
    const int*   x     = (const int*)  d_in[0];
    const float* embed = (const float*)d_in[1];
    const float* Wxh_w = (const float*)d_in[2];
    const float* Wxh_b = (const float*)d_in[3];
    const float* Whh_w = (const float*)d_in[4];
    const float* Whh_b = (const float*)d_in[5];
    const float* fc_w  = (const float*)d_in[6];
    const float* fc_b  = (const float*)d_in[7];
    float* outp = (float*)d_out;

    float* P;
    __half *hhi, *hlos, *whhhi, *whhlos, *wxhhi, *wxhlos, *embhi, *emblos, *fchi, *fclos;
    cudaGetSymbolAddress((void**)&P,      g_P);
    cudaGetSymbolAddress((void**)&hhi,    g_hhi);
    cudaGetSymbolAddress((void**)&hlos,   g_hlos);
    cudaGetSymbolAddress((void**)&whhhi,  g_whhhi);
    cudaGetSymbolAddress((void**)&whhlos, g_whhlos);
    cudaGetSymbolAddress((void**)&wxhhi,  g_wxhhi);
    cudaGetSymbolAddress((void**)&wxhlos, g_wxhlos);
    cudaGetSymbolAddress((void**)&embhi,  g_embhi);
    cudaGetSymbolAddress((void**)&emblos, g_emblos);
    cudaGetSymbolAddress((void**)&fchi,   g_fchi);
    cudaGetSymbolAddress((void**)&fclos,  g_fclos);

    const int SM_P   = (2 * 32 + 2 * 64) * 128 * 4 + 1024;    //  97 KB
    const int SM_RNN = 131072 + 3 * 32768 + 1024;             // 225 KB
    cudaFuncSetAttribute(k_g3<32, 64, 2, 4>,
                         cudaFuncAttributeMaxDynamicSharedMemorySize, SM_P);
    cudaFuncSetAttribute(k_fused,
                         cudaFuncAttributeMaxDynamicSharedMemorySize, SM_RNN);

    // 0) operand splits + barrier reset (single kernel)
    k_split_all<<<(HID * HID) / 256, 256>>>(Whh_w, whhhi, whhlos,
                                            Wxh_w, wxhhi, wxhlos,
                                            fc_w, fchi, fclos,
                                            embed, embhi, emblos);

    // 1) P = embed @ Wxh^T + bxh
    k_g3<32, 64, 2, 4><<<dim3(HID / 64, VOCABN / 32), 256, SM_P>>>(
        embhi, emblos, wxhhi, wxhlos, Wxh_b, P);

    // 2) t = 0
    k_step0<<<(BATCHN * HID) / 256, 256>>>(x, P, Whh_b, hhi, hlos);

    // 3) fused persistent: recurrence + tail fc + fc consumers
    k_fused<<<NCTA + NFC, 256, SM_RNN>>>(whhhi, whhlos, Whh_b, P, x, hhi, hlos,
                                         fchi, fclos, fc_b, outp);
}

// round 17
// speedup vs baseline: 1.1174x; 1.0590x over previous
#include <cuda_runtime.h>
#include <cuda_fp16.h>
#include <math.h>
#include <stdint.h>

#define VOCABN 128
#define HID    1024
#define BATCHN 256
#define SEQ    256
#define NCTA   128     // recurrence CTAs
#define NFC    20      // fc consumer CTAs
#define GRPSZ  16u
#define TFC    240     // fc consumers cover t < TFC; rnn CTAs cover the rest

// ---------------- device scratch (no allocations allowed) ----------------
__device__ float    g_P[VOCABN * HID];               // emb@Wxh^T + bxh + bhh
__device__ __half   g_hhi [(size_t)SEQ * BATCHN * HID];
__device__ __half   g_hlos[(size_t)SEQ * BATCHN * HID];
__device__ __half   g_whhhi[HID * HID], g_whhlos[HID * HID];
__device__ __half   g_wxhhi[HID * HID], g_wxhlos[HID * HID];
__device__ __half   g_embhi[VOCABN * HID], g_emblos[VOCABN * HID];
__device__ __half   g_fchi[VOCABN * HID],  g_fclos[VOCABN * HID];
__device__ unsigned g_bar[SEQ * 8];                  // per-(step, m-group) counters

// ---------------- PTX helpers ----------------
__device__ __forceinline__ uint32_t smem_u32(const void* p) {
    uint32_t a;
    asm("{ .reg .u64 t; cvta.to.shared.u64 t, %1; cvt.u32.u64 %0, t; }" : "=r"(a) : "l"(p));
    return a;
}
__device__ __forceinline__ uint32_t swz(uint32_t o) { return o ^ ((o >> 3) & 0x70); }

// fast tanh: exp-based, abs err ~1e-6
__device__ __forceinline__ float ftanh(float x) {
    float xc = fminf(fmaxf(x, -9.f), 9.f);
    float e  = __expf(xc + xc);
    return __fdividef(e - 1.f, e + 1.f);
}

#define CP_ASYNC16(dst, src) \
    asm volatile("cp.async.cg.shared.global [%0], [%1], 16;" :: "r"(dst), "l"(src) : "memory")
#define CP_COMMIT() asm volatile("cp.async.commit_group;" ::: "memory")
#define CP_WAIT2()  asm volatile("cp.async.wait_group 2;" ::: "memory")
#define CP_WAIT1()  asm volatile("cp.async.wait_group 1;" ::: "memory")
#define CP_WAIT0()  asm volatile("cp.async.wait_group 0;" ::: "memory")

#define LDSM4(r, addr)                                                            \
    asm volatile("ldmatrix.sync.aligned.m8n8.x4.shared.b16 {%0,%1,%2,%3}, [%4];"  \
        : "=r"((r)[0]), "=r"((r)[1]), "=r"((r)[2]), "=r"((r)[3]) : "r"(addr))

// fp32-accumulate mma (main term — exact)
#define MMA16816(c, a, b0, b1)                                                    \
    asm volatile("mma.sync.aligned.m16n8k16.row.col.f32.f16.f16.f32 "             \
        "{%0,%1,%2,%3},{%4,%5,%6,%7},{%8,%9},{%0,%1,%2,%3};"                      \
        : "+f"((c)[0]), "+f"((c)[1]), "+f"((c)[2]), "+f"((c)[3])                   \
        : "r"((a)[0]), "r"((a)[1]), "r"((a)[2]), "r"((a)[3]), "r"(b0), "r"(b1))

// fp16-accumulate mma (correction terms)
#define MMA16816H(c, a, b0, b1)                                                   \
    asm volatile("mma.sync.aligned.m16n8k16.row.col.f16.f16.f16.f16 "             \
        "{%0,%1},{%2,%3,%4,%5},{%6,%7},{%0,%1};"                                  \
        : "+r"((c)[0]), "+r"((c)[1])                                              \
        : "r"((a)[0]), "r"((a)[1]), "r"((a)[2]), "r"((a)[3]), "r"(b0), "r"(b1))

__device__ __forceinline__ void poll_group(const unsigned* slot, int sleep_ns) {
    unsigned v;
    while (true) {
        asm volatile("ld.acquire.gpu.global.u32 %0, [%1];"
                     : "=r"(v) : "l"(slot) : "memory");
        if (v >= GRPSZ) break;
        __nanosleep(sleep_ns);
    }
}

// ===========================================================================
// RNN loaders. Big chunk = K=128 = two 16KB halves, slot = bk % 3 (32KB each).
// Half layout: [Ahi fp16 4KB | Alo fp16 4KB | Wlos fp16 8KB], all SW128.
// ===========================================================================
__device__ __forceinline__ void rnn_load_W2(
    uint32_t STG, int tid, int bk, const __half* __restrict__ Wlos, int n0)
{
    const uint32_t stg0 = STG + (uint32_t)(bk % 3) * 32768;
    const int r = tid >> 3, cc = tid & 7;
#pragma unroll
    for (int sub = 0; sub < 2; sub++) {
        const int kb = (bk * 2 + sub) * 64 + cc * 8;
        const uint32_t stg = stg0 + (uint32_t)sub * 16384;
        CP_ASYNC16(stg + 8192 + swz((uint32_t)(r * 128 + cc * 16)),
                   Wlos + (size_t)(n0 + r) * HID + kb);
        CP_ASYNC16(stg + 8192 + swz((uint32_t)((r + 32) * 128 + cc * 16)),
                   Wlos + (size_t)(n0 + r + 32) * HID + kb);
    }
    CP_COMMIT();
}

__device__ __forceinline__ void rnn_load_A2(
    uint32_t STG, int tid, int bk,
    const __half* __restrict__ Ahi, const __half* __restrict__ Alo, size_t m0)
{
    const uint32_t stg0 = STG + (uint32_t)(bk % 3) * 32768;
    const int r = tid >> 3, cc = tid & 7;
    const uint32_t off = swz((uint32_t)(r * 128 + cc * 16));
#pragma unroll
    for (int sub = 0; sub < 2; sub++) {
        const int kb = (bk * 2 + sub) * 64 + cc * 8;
        const uint32_t stg = stg0 + (uint32_t)sub * 16384;
        CP_ASYNC16(stg + off,        Ahi + (m0 + r) * (size_t)HID + kb);
        CP_ASYNC16(stg + 4096 + off, Alo + (m0 + r) * (size_t)HID + kb);
    }
    CP_COMMIT();
}

__device__ __forceinline__ void rnn_load_full2(
    uint32_t STG, int tid, int bk,
    const __half* __restrict__ Ahi, const __half* __restrict__ Alo,
    const __half* __restrict__ Wlos, size_t m0, int n0)
{
    const uint32_t stg0 = STG + (uint32_t)(bk % 3) * 32768;
    const int r = tid >> 3, cc = tid & 7;
    const uint32_t off = swz((uint32_t)(r * 128 + cc * 16));
#pragma unroll
    for (int sub = 0; sub < 2; sub++) {
        const int kb = (bk * 2 + sub) * 64 + cc * 8;
        const uint32_t stg = stg0 + (uint32_t)sub * 16384;
        CP_ASYNC16(stg + off,        Ahi + (m0 + r) * (size_t)HID + kb);
        CP_ASYNC16(stg + 4096 + off, Alo + (m0 + r) * (size_t)HID + kb);
        CP_ASYNC16(stg + 8192 + off, Wlos + (size_t)(n0 + r) * HID + kb);
        CP_ASYNC16(stg + 8192 + swz((uint32_t)((r + 32) * 128 + cc * 16)),
                   Wlos + (size_t)(n0 + r + 32) * HID + kb);
    }
    CP_COMMIT();
}

// ---- fc consumer loader: half unit, A = 128 rows, B = 128 rows ----
__device__ __forceinline__ void fc_load(
    uint32_t FST, int tid, int slot, int c,
    const __half* __restrict__ Ahi, const __half* __restrict__ Alos,
    const __half* __restrict__ Bhi, const __half* __restrict__ Blos)
{
    const int seg = c >> 4;
    const __half* A = (seg == 2) ? Alos : Ahi;
    const __half* B = (seg == 1) ? Blos : Bhi;
    const uint32_t stg = FST + (uint32_t)slot * 32768;
#pragma unroll
    for (int i = 0; i < 4; i++) {
        int id = tid + i * 256, r = id >> 3;
        uint32_t off = swz((uint32_t)(r * 128 + (id & 7) * 16));
        CP_ASYNC16(stg + off, A + (size_t)r * HID + (c & 15) * 64 + (id & 7) * 8);
    }
#pragma unroll
    for (int i = 0; i < 4; i++) {
        int id = tid + i * 256, r = id >> 3;
        uint32_t off = swz((uint32_t)(r * 128 + (id & 7) * 16));
        CP_ASYNC16(stg + 16384 + off, B + (size_t)r * HID + (c & 15) * 64 + (id & 7) * 8);
    }
    CP_COMMIT();
}

// ---- tail fc loader: A = 32 rows, B = 128 rows. Stage 20KB x 4. ----
__device__ __forceinline__ void tail_load(
    uint32_t FST, int tid, int slot, int c,
    const __half* __restrict__ Ahi, const __half* __restrict__ Alos,
    const __half* __restrict__ Bhi, const __half* __restrict__ Blos)
{
    const int seg = c >> 4;
    const __half* A = (seg == 2) ? Alos : Ahi;
    const __half* B = (seg == 1) ? Blos : Bhi;
    const uint32_t stg = FST + (uint32_t)slot * 20480;
    {
        int r = tid >> 3;
        uint32_t off = swz((uint32_t)(r * 128 + (tid & 7) * 16));
        CP_ASYNC16(stg + off, A + (size_t)r * HID + (c & 15) * 64 + (tid & 7) * 8);
    }
#pragma unroll
    for (int i = 0; i < 4; i++) {
        int id = tid + i * 256, r = id >> 3;
        uint32_t off = swz((uint32_t)(r * 128 + (id & 7) * 16));
        CP_ASYNC16(stg + 4096 + off, B + (size_t)r * HID + (c & 15) * 64 + (id & 7) * 8);
    }
    CP_COMMIT();
}

// ===========================================================================
// Fused persistent kernel: CTAs 0..127 recurrence then a tail-fc sliver each;
// CTAs 128..147 fc consumers for t < TFC.
// ===========================================================================
__global__ __launch_bounds__(256, 1)
void k_fused(const __half* __restrict__ Whi, const __half* __restrict__ Wlos,
             const float* __restrict__ P,
             const int* __restrict__ x,
             __half* __restrict__ hhi, __half* __restrict__ hlos,
             const __half* __restrict__ FChi, const __half* __restrict__ FClos,
             const float* __restrict__ fcb, float* __restrict__ outp)
{
    extern __shared__ char smem_raw[];
    const uint32_t sb  = (smem_u32(smem_raw) + 1023u) & ~1023u;
    const int tid = threadIdx.x;
    const int wid = tid >> 5, lane = tid & 31;
    const int g = lane >> 2, t4 = lane & 3;
    const size_t SLOT = (size_t)BATCHN * HID;

    if (blockIdx.x < NCTA) {
        // =================== RNN path ===================
        const uint32_t PIN = sb;                 // 16 x 8KB pinned Whi
        const uint32_t STG = sb + 131072;        // 3 x 32KB stages
        const int wm  = wid >> 2, wn = wid & 3;
        const int grp = blockIdx.x >> 4;
        const size_t m0 = (size_t)grp * 32;
        const int    n0 = (blockIdx.x & 15) * 64;

        {
            const int r = tid >> 3, cc = tid & 7;
#pragma unroll 1
            for (int k0 = 0; k0 < 16; k0++) {
#pragma unroll
                for (int p = 0; p < 2; p++) {
                    int rr = r + p * 32;
                    CP_ASYNC16(PIN + k0 * 8192 + swz((uint32_t)(rr * 128 + cc * 16)),
                               Whi + (size_t)(n0 + rr) * HID + k0 * 64 + cc * 8);
                }
            }
            CP_COMMIT(); CP_WAIT0();
        }
        __syncthreads();

        rnn_load_W2(STG, tid, 0, Wlos, n0);

        const size_t mr0 = m0 + wm * 16 + g;     // fixed epilogue rows

#pragma unroll 1
        for (int t = 1; t < SEQ; t++) {
            if (t > 1) {
                if (tid == 0) poll_group(&g_bar[(t - 1) * 8 + grp], 16);
                __syncthreads();
            }

            // ---- prefetch epilogue operands (P-gather hidden under MMA) ----
            const int xr0 = x[mr0 * SEQ + t];
            const int xr1 = x[(mr0 + 8) * SEQ + t];
            float2 pv[2][2];                     // [h2][nf]
#pragma unroll
            for (int nf = 0; nf < 2; nf++) {
                const int n = n0 + wn * 16 + nf * 8 + t4 * 2;
                pv[0][nf] = *(const float2*)(P + (size_t)xr0 * HID + n);
                pv[1][nf] = *(const float2*)(P + (size_t)xr1 * HID + n);
            }

            const __half* Ahi = hhi  + (size_t)(t - 1) * SLOT;
            const __half* Alo = hlos + (size_t)(t - 1) * SLOT;
            rnn_load_A2(STG, tid, 0, Ahi, Alo, m0);
            rnn_load_full2(STG, tid, 1, Ahi, Alo, Wlos, m0, n0);

            float    acc0[2][4];
            uint32_t ach1[2][2], ach2[2][2];
#pragma unroll
            for (int j = 0; j < 2; j++) {
#pragma unroll
                for (int q = 0; q < 4; q++) acc0[j][q] = 0.f;
                ach1[j][0] = 0u; ach1[j][1] = 0u;
                ach2[j][0] = 0u; ach2[j][1] = 0u;
            }

#pragma unroll 1
            for (int k = 0; k < 8; k++) {
                if (k < 7) CP_WAIT1(); else CP_WAIT0();
                __syncthreads();
                if (k + 2 < 8)
                    rnn_load_full2(STG, tid, k + 2, Ahi, Alo, Wlos, m0, n0);
                const uint32_t stg0 = STG + (uint32_t)(k % 3) * 32768;
#pragma unroll
                for (int sub = 0; sub < 2; sub++) {
                    const uint32_t stg  = stg0 + (uint32_t)sub * 16384;
                    const uint32_t pinc = PIN + (uint32_t)(k * 2 + sub) * 8192;
#pragma unroll
                    for (int kk = 0; kk < 4; kk++) {
                        uint32_t afh[4], afl[4], bfh[4], bfl[4];
                        {
                            const int r0 = wm * 16 + (lane & 15);
                            const int c2 = (kk * 16 + (lane >> 4) * 8) * 2;
                            const uint32_t off = swz((uint32_t)(r0 * 128 + c2));
                            LDSM4(afh, stg + off);
                            LDSM4(afl, stg + 4096 + off);
                        }
                        {
                            const int r0 = wn * 16 + (lane & 7) + ((lane >> 4) << 3);
                            const int c2 = (kk * 16 + ((lane >> 3) & 1) * 8) * 2;
                            const uint32_t off = swz((uint32_t)(r0 * 128 + c2));
                            LDSM4(bfh, pinc + off);
                            LDSM4(bfl, stg + 8192 + off);
                        }
                        MMA16816(acc0[0], afh, bfh[0], bfh[1]);   // hi*hi
                        MMA16816(acc0[1], afh, bfh[2], bfh[3]);
                        MMA16816H(ach1[0], afh, bfl[0], bfl[1]);  // hi*wlo
                        MMA16816H(ach1[1], afh, bfl[2], bfl[3]);
                        MMA16816H(ach2[0], afl, bfh[0], bfh[1]);  // lo*whi
                        MMA16816H(ach2[1], afl, bfh[2], bfh[3]);
                    }
                }
            }

            // W prefetch chunk 0 of next step (slot 0 freed at iter-7 sync)
            if (t + 1 < SEQ)
                rnn_load_W2(STG, tid, 0, Wlos, n0);

            __half* dhi = hhi  + (size_t)t * SLOT;
            __half* dlo = hlos + (size_t)t * SLOT;
            float* hid = outp + (size_t)BATCHN * SEQ * VOCABN;
#pragma unroll
            for (int nf = 0; nf < 2; nf++) {
                const int n = n0 + wn * 16 + nf * 8 + t4 * 2;
#pragma unroll
                for (int h2 = 0; h2 < 2; h2++) {
                    const size_t m = mr0 + h2 * 8;
                    const __half2 c1 = *reinterpret_cast<const __half2*>(&ach1[nf][h2]);
                    const __half2 c2 = *reinterpret_cast<const __half2*>(&ach2[nf][h2]);
                    float v0 = acc0[nf][h2 * 2] +
                               0.03125f * (__low2float(c1)  + __low2float(c2)) +
                               pv[h2][nf].x;
                    float v1 = acc0[nf][h2 * 2 + 1] +
                               0.03125f * (__high2float(c1) + __high2float(c2)) +
                               pv[h2][nf].y;
                    const float h0 = ftanh(v0), h1 = ftanh(v1);
                    const __half a0 = __float2half_rn(h0), a1 = __float2half_rn(h1);
                    const float f0 = __half2float(a0), f1 = __half2float(a1);
                    *(__half2*)(dhi + m * HID + n) = __halves2half2(a0, a1);
                    *(__half2*)(dlo + m * HID + n) =
                        __halves2half2(__float2half_rn((h0 - f0) * 32.f),
                                       __float2half_rn((h1 - f1) * 32.f));
                    if (t == SEQ - 1) {
                        float2 o; o.x = h0; o.y = h1;
                        *(float2*)(hid + m * HID + n) = o;
                    }
                }
            }

            // bar.sync gives CTA-scope hb from all threads' stores to tid0;
            // red.release.gpu provides the gpu-scope release edge. No membar.
            __syncthreads();
            if (tid == 0)
                asm volatile("red.release.gpu.global.add.u32 [%0], %1;"
                             :: "l"(&g_bar[t * 8 + grp]), "r"(1u) : "memory");
        }

        // ========== tail: fc sliver for t in [TFC, SEQ) ==========
        {
            const int tt   = TFC + (blockIdx.x >> 3);
            const int mg   = blockIdx.x & 7;
            const int mrow = mg * 32;
            if (tid == 0) poll_group(&g_bar[tt * 8 + mg], 64);
            __syncthreads();

            const __half* Ah = hhi  + (size_t)tt * SLOT + (size_t)mrow * HID;
            const __half* Al = hlos + (size_t)tt * SLOT + (size_t)mrow * HID;
            const uint32_t FST = sb;
            const int twm = wid >> 2, twn = wid & 3;

            tail_load(FST, tid, 0, 0, Ah, Al, FChi, FClos);
            tail_load(FST, tid, 1, 1, Ah, Al, FChi, FClos);
            tail_load(FST, tid, 2, 2, Ah, Al, FChi, FClos);

            float    accA[4][4];
            uint32_t accBh[4][2];
#pragma unroll
            for (int j = 0; j < 4; j++) {
#pragma unroll
                for (int q = 0; q < 4; q++) accA[j][q] = 0.f;
                accBh[j][0] = 0u; accBh[j][1] = 0u;
            }

#pragma unroll 1
            for (int c = 0; c < 48; c++) {
                if (c < 46)       CP_WAIT2();
                else if (c == 46) CP_WAIT1();
                else              CP_WAIT0();
                __syncthreads();
                if (c + 3 < 48)
                    tail_load(FST, tid, (c + 3) & 3, c + 3, Ah, Al, FChi, FClos);

                const uint32_t stg = FST + (uint32_t)(c & 3) * 20480;
                const bool mainseg = (c >> 4) == 0;
#pragma unroll
                for (int kk = 0; kk < 4; kk++) {
                    uint32_t af[4], bf[2][4];
                    {
                        const int r0 = twm * 16 + (lane & 15);
                        const int c2 = (kk * 16 + (lane >> 4) * 8) * 2;
                        LDSM4(af, stg + swz((uint32_t)(r0 * 128 + c2)));
                    }
                    {
                        const int r0 = twn * 32 + (lane & 7) + ((lane >> 4) << 3);
                        const int c2 = (kk * 16 + ((lane >> 3) & 1) * 8) * 2;
#pragma unroll
                        for (int np = 0; np < 2; np++)
                            LDSM4(bf[np], stg + 4096 +
                                          swz((uint32_t)((r0 + np * 16) * 128 + c2)));
                    }
                    if (mainseg) {
#pragma unroll
                        for (int np = 0; np < 2; np++) {
                            MMA16816(accA[np * 2],     af, bf[np][0], bf[np][1]);
                            MMA16816(accA[np * 2 + 1], af, bf[np][2], bf[np][3]);
                        }
                    } else {
#pragma unroll
                        for (int np = 0; np < 2; np++) {
                            MMA16816H(accBh[np * 2],     af, bf[np][0], bf[np][1]);
                            MMA16816H(accBh[np * 2 + 1], af, bf[np][2], bf[np][3]);
                        }
                    }
                }
            }

#pragma unroll
            for (int nf = 0; nf < 4; nf++) {
                const int n = twn * 32 + (nf >> 1) * 16 + (nf & 1) * 8 + t4 * 2;
                const float b0 = fcb[n], b1 = fcb[n + 1];
#pragma unroll
                for (int h2 = 0; h2 < 2; h2++) {
                    const int mloc = twm * 16 + g + h2 * 8;
                    const size_t b = (size_t)mrow + mloc;
                    const __half2 cb =
                        *reinterpret_cast<const __half2*>(&accBh[nf][h2]);
                    float2 o;
                    o.x = accA[nf][h2 * 2]     + 0.03125f * __low2float(cb)  + b0;
                    o.y = accA[nf][h2 * 2 + 1] + 0.03125f * __high2float(cb) + b1;
                    *(float2*)(outp + (b * SEQ + tt) * VOCABN + n) = o;
                }
            }
        }
        return;
    }

    // ======================= fc consumer path (t < TFC, half units) ========
    const int cta = blockIdx.x - NCTA;
    const uint32_t FST = sb;
    const int wm = wid >> 1, wn = wid & 1;
    const int gg = lane >> 2;

#pragma unroll 1
    for (int u = cta; u < 2 * TFC; u += NFC) {
        const int t = u >> 1, bh = u & 1;

        if (t >= 1) {
            if (tid < 4) poll_group(&g_bar[t * 8 + bh * 4 + tid], 128);
        }
        __syncthreads();

        const __half* Ah = hhi  + (size_t)t * SLOT + (size_t)bh * 128 * HID;
        const __half* Al = hlos + (size_t)t * SLOT + (size_t)bh * 128 * HID;

        fc_load(FST, tid, 0, 0, Ah, Al, FChi, FClos);
        fc_load(FST, tid, 1, 1, Ah, Al, FChi, FClos);
        fc_load(FST, tid, 2, 2, Ah, Al, FChi, FClos);

        float    accA[2][8][4];
        uint32_t accBh[2][8][2];
#pragma unroll
        for (int i = 0; i < 2; i++)
#pragma unroll
            for (int j = 0; j < 8; j++) {
#pragma unroll
                for (int q = 0; q < 4; q++) accA[i][j][q] = 0.f;
                accBh[i][j][0] = 0u; accBh[i][j][1] = 0u;
            }

#pragma unroll 1
        for (int c = 0; c < 48; c++) {
            if (c < 46)       CP_WAIT2();
            else if (c == 46) CP_WAIT1();
            else              CP_WAIT0();
            __syncthreads();
            if (c + 3 < 48)
                fc_load(FST, tid, (c + 3) & 3, c + 3, Ah, Al, FChi, FClos);

            const uint32_t stg = FST + (uint32_t)(c & 3) * 32768;
            const bool mainseg = (c >> 4) == 0;
#pragma unroll
            for (int kk = 0; kk < 4; kk++) {
                uint32_t af[2][4], bf[4][4];
                {
                    const int r0 = wm * 32 + (lane & 15);
                    const int c2 = (kk * 16 + (lane >> 4) * 8) * 2;
#pragma unroll
                    for (int mf = 0; mf < 2; mf++)
                        LDSM4(af[mf], stg + swz((uint32_t)((r0 + mf * 16) * 128 + c2)));
                }
                {
                    const int r0 = wn * 64 + (lane & 7) + ((lane >> 4) << 3);
                    const int c2 = (kk * 16 + ((lane >> 3) & 1) * 8) * 2;
#pragma unroll
                    for (int np = 0; np < 4; np++)
                        LDSM4(bf[np], stg + 16384 +
                                      swz((uint32_t)((r0 + np * 16) * 128 + c2)));
                }
                if (mainseg) {
#pragma unroll
                    for (int mf = 0; mf < 2; mf++)
#pragma unroll
                        for (int np = 0; np < 4; np++) {
                            MMA16816(accA[mf][np * 2],     af[mf], bf[np][0], bf[np][1]);
                            MMA16816(accA[mf][np * 2 + 1], af[mf], bf[np][2], bf[np][3]);
                        }
                } else {
#pragma unroll
                    for (int mf = 0; mf < 2; mf++)
#pragma unroll
                        for (int np = 0; np < 4; np++) {
                            MMA16816H(accBh[mf][np * 2],     af[mf], bf[np][0], bf[np][1]);
                            MMA16816H(accBh[mf][np * 2 + 1], af[mf], bf[np][2], bf[np][3]);
                        }
                }
            }
        }

#pragma unroll
        for (int mf = 0; mf < 2; mf++) {
#pragma unroll
            for (int nf = 0; nf < 8; nf++) {
                const int n = wn * 64 + (nf >> 1) * 16 + (nf & 1) * 8 + t4 * 2;
                const float b0 = fcb[n], b1 = fcb[n + 1];
#pragma unroll
                for (int h2 = 0; h2 < 2; h2++) {
                    const int mloc = wm * 32 + mf * 16 + gg + h2 * 8;
                    const size_t b = (size_t)bh * 128 + mloc;
                    const __half2 cb =
                        *reinterpret_cast<const __half2*>(&accBh[mf][nf][h2]);
                    float2 o;
                    o.x = accA[mf][nf][h2 * 2]     + 0.03125f * __low2float(cb)  + b0;
                    o.y = accA[mf][nf][h2 * 2 + 1] + 0.03125f * __high2float(cb) + b1;
                    *(float2*)(outp + (b * SEQ + t) * VOCABN + n) = o;
                }
            }
        }
        __syncthreads();
    }
}

// ===========================================================================
// Generic streaming 3-split GEMM (P precompute only). Adds bias1 + bias2.
// ===========================================================================
__device__ __forceinline__ void wait_chunk(int k0) {
    if (k0 < 14)       CP_WAIT2();
    else if (k0 == 14) CP_WAIT1();
    else               CP_WAIT0();
}

template<int BM, int BN>
__device__ __forceinline__ void g3_load(
    uint32_t STG, int tid, int k0, size_t m0, int n0,
    const __half* __restrict__ Ahi, const __half* __restrict__ Alos,
    const __half* __restrict__ Bhi, const __half* __restrict__ Blos)
{
    constexpr int STAGE = (2 * BM + 2 * BN) * 128;
    const uint32_t stg = STG + (uint32_t)(k0 & 3) * STAGE;
#pragma unroll
    for (int i = 0; i < BM * 8 / 256; i++) {
        int id = tid + i * 256, r = id >> 3, cc = id & 7;
        int kb = k0 * 64 + cc * 8;
        uint32_t off = swz((uint32_t)(r * 128 + cc * 16));
        CP_ASYNC16(stg + off,            Ahi  + (m0 + r) * (size_t)HID + kb);
        CP_ASYNC16(stg + BM * 128 + off, Alos + (m0 + r) * (size_t)HID + kb);
    }
#pragma unroll
    for (int i = 0; i < BN * 8 / 256; i++) {
        int id = tid + i * 256, r = id >> 3, cc = id & 7;
        int kb = k0 * 64 + cc * 8;
        uint32_t off = swz((uint32_t)(r * 128 + cc * 16));
        CP_ASYNC16(stg + 2 * BM * 128 + off,            Bhi  + (size_t)(n0 + r) * HID + kb);
        CP_ASYNC16(stg + 2 * BM * 128 + BN * 128 + off, Blos + (size_t)(n0 + r) * HID + kb);
    }
    CP_COMMIT();
}

template<int BM, int BN, int WM, int WN>
__global__ __launch_bounds__(256, 1)
void k_g3(const __half* __restrict__ Ahi, const __half* __restrict__ Alos,
          const __half* __restrict__ Bhi, const __half* __restrict__ Blos,
          const float* __restrict__ bias1, const float* __restrict__ bias2,
          float* __restrict__ Cf)
{
    constexpr int TM = BM / WM, TN = BN / WN;
    constexpr int MF = TM / 16, NF2 = TN / 16;
    constexpr int STAGE = (2 * BM + 2 * BN) * 128;

    extern __shared__ char smem_raw[];
    const uint32_t sb = (smem_u32(smem_raw) + 1023u) & ~1023u;
    const int tid = threadIdx.x, wid = tid >> 5, lane = tid & 31;
    const int wm = wid / WN, wn = wid % WN;
    const int n0 = blockIdx.x * BN;
    const size_t m0 = (size_t)blockIdx.y * BM;

    float acc[3][MF][NF2 * 2][4];
#pragma unroll
    for (int s = 0; s < 3; s++)
#pragma unroll
        for (int i = 0; i < MF; i++)
#pragma unroll
            for (int j = 0; j < NF2 * 2; j++)
#pragma unroll
                for (int q = 0; q < 4; q++) acc[s][i][j][q] = 0.f;

    g3_load<BM, BN>(sb, tid, 0, m0, n0, Ahi, Alos, Bhi, Blos);
    g3_load<BM, BN>(sb, tid, 1, m0, n0, Ahi, Alos, Bhi, Blos);
    g3_load<BM, BN>(sb, tid, 2, m0, n0, Ahi, Alos, Bhi, Blos);

#pragma unroll 1
    for (int k0 = 0; k0 < 16; k0++) {
        wait_chunk(k0);
        __syncthreads();
        if (k0 + 3 < 16)
            g3_load<BM, BN>(sb, tid, k0 + 3, m0, n0, Ahi, Alos, Bhi, Blos);
        const uint32_t stg = sb + (uint32_t)(k0 & 3) * STAGE;
        const uint32_t aH = stg, aL = stg + BM * 128;
        const uint32_t bH = stg + 2 * BM * 128, bL = bH + BN * 128;
#pragma unroll
        for (int kk = 0; kk < 4; kk++) {
            uint32_t afh[MF][4], afl[MF][4], bfh[NF2][4], bfl[NF2][4];
            {
                const int r0 = wm * TM + (lane & 15);
                const int c2 = (kk * 16 + (lane >> 4) * 8) * 2;
#pragma unroll
                for (int mf = 0; mf < MF; mf++) {
                    uint32_t off = swz((uint32_t)((r0 + mf * 16) * 128 + c2));
                    LDSM4(afh[mf], aH + off);
                    LDSM4(afl[mf], aL + off);
                }
            }
            {
                const int r0 = wn * TN + (lane & 7) + ((lane >> 4) << 3);
                const int c2 = (kk * 16 + ((lane >> 3) & 1) * 8) * 2;
#pragma unroll
                for (int np = 0; np < NF2; np++) {
                    uint32_t off = swz((uint32_t)((r0 + np * 16) * 128 + c2));
                    LDSM4(bfh[np], bH + off);
                    LDSM4(bfl[np], bL + off);
                }
            }
#pragma unroll
            for (int mf = 0; mf < MF; mf++)
#pragma unroll
                for (int np = 0; np < NF2; np++) {
                    MMA16816(acc[0][mf][np * 2],     afh[mf], bfh[np][0], bfh[np][1]);
                    MMA16816(acc[0][mf][np * 2 + 1], afh[mf], bfh[np][2], bfh[np][3]);
                    MMA16816(acc[1][mf][np * 2],     afh[mf], bfl[np][0], bfl[np][1]);
                    MMA16816(acc[1][mf][np * 2 + 1], afh[mf], bfl[np][2], bfl[np][3]);
                    MMA16816(acc[2][mf][np * 2],     afl[mf], bfh[np][0], bfh[np][1]);
                    MMA16816(acc[2][mf][np * 2 + 1], afl[mf], bfh[np][2], bfh[np][3]);
                }
        }
    }

    const int g = lane >> 2, t4 = lane & 3;
#pragma unroll
    for (int mf = 0; mf < MF; mf++) {
#pragma unroll
        for (int nf = 0; nf < NF2 * 2; nf++) {
            const int n = n0 + wn * TN + (nf >> 1) * 16 + (nf & 1) * 8 + t4 * 2;
            const float b0 = bias1[n] + bias2[n], b1 = bias1[n + 1] + bias2[n + 1];
#pragma unroll
            for (int h2 = 0; h2 < 2; h2++) {
                const size_t m = m0 + wm * TM + mf * 16 + g + h2 * 8;
                float2 o;
                o.x = acc[0][mf][nf][h2 * 2] +
                      0.03125f * (acc[1][mf][nf][h2 * 2] + acc[2][mf][nf][h2 * 2]) + b0;
                o.y = acc[0][mf][nf][h2 * 2 + 1] +
                      0.03125f * (acc[1][mf][nf][h2 * 2 + 1] + acc[2][mf][nf][h2 * 2 + 1]) + b1;
                *(float2*)(Cf + m * HID + n) = o;
            }
        }
    }
}

// ---------------- small kernels ----------------
__global__ __launch_bounds__(256)
void k_split_all(const float* __restrict__ whh, __half* __restrict__ whhhi,
                 __half* __restrict__ whhlos,
                 const float* __restrict__ wxh, __half* __restrict__ wxhhi,
                 __half* __restrict__ wxhlos,
                 const float* __restrict__ fcw, __half* __restrict__ fchi,
                 __half* __restrict__ fclos,
                 const float* __restrict__ emb, __half* __restrict__ embhi,
                 __half* __restrict__ emblos)
{
    int i = blockIdx.x * 256 + threadIdx.x;
    if (i < SEQ * 8) g_bar[i] = 0;
    {
        float v = whh[i];
        __half h = __float2half_rn(v);
        whhhi[i]  = h;
        whhlos[i] = __float2half_rn((v - __half2float(h)) * 32.f);
    }
    {
        float v = wxh[i];
        __half h = __float2half_rn(v);
        wxhhi[i]  = h;
        wxhlos[i] = __float2half_rn((v - __half2float(h)) * 32.f);
    }
    if (i < VOCABN * HID) {
        {
            float v = fcw[i];
            __half h = __float2half_rn(v);
            fchi[i]  = h;
            fclos[i] = __float2half_rn((v - __half2float(h)) * 32.f);
        }
        {
            float v = emb[i];
            __half h = __float2half_rn(v);
            embhi[i]  = h;
            emblos[i] = __float2half_rn((v - __half2float(h)) * 32.f);
        }
    }
}

__global__ __launch_bounds__(256)
void k_step0(const int* __restrict__ x, const float* __restrict__ P,
             __half* __restrict__ hhi, __half* __restrict__ hlos)
{
    int idx = blockIdx.x * 256 + threadIdx.x;
    int b = idx >> 10, n = idx & (HID - 1);
    float h = ftanh(P[(size_t)x[b * SEQ] * HID + n]);   // P already has both biases
    __half a = __float2half_rn(h);
    hhi[idx]  = a;
    hlos[idx] = __float2half_rn((h - __half2float(a)) * 32.f);
}

extern "C" void kernel_launch(void* const* d_in, const int* in_sizes, int n_in,
                              void* d_out, int out_size)
{
    const int*   x     = (const int*)  d_in[0];
    const float* embed = (const float*)d_in[1];
    const float* Wxh_w = (const float*)d_in[2];
    const float* Wxh_b = (const float*)d_in[3];
    const float* Whh_w = (const float*)d_in[4];
    const float* Whh_b = (const float*)d_in[5];
    const float* fc_w  = (const float*)d_in[6];
    const float* fc_b  = (const float*)d_in[7];
    float* outp = (float*)d_out;

    float* P;
    __half *hhi, *hlos, *whhhi, *whhlos, *wxhhi, *wxhlos, *embhi, *emblos, *fchi, *fclos;
    cudaGetSymbolAddress((void**)&P,      g_P);
    cudaGetSymbolAddress((void**)&hhi,    g_hhi);
    cudaGetSymbolAddress((void**)&hlos,   g_hlos);
    cudaGetSymbolAddress((void**)&whhhi,  g_whhhi);
    cudaGetSymbolAddress((void**)&whhlos, g_whhlos);
    cudaGetSymbolAddress((void**)&wxhhi,  g_wxhhi);
    cudaGetSymbolAddress((void**)&wxhlos, g_wxhlos);
    cudaGetSymbolAddress((void**)&embhi,  g_embhi);
    cudaGetSymbolAddress((void**)&emblos, g_emblos);
    cudaGetSymbolAddress((void**)&fchi,   g_fchi);
    cudaGetSymbolAddress((void**)&fclos,  g_fclos);

    const int SM_P   = (2 * 32 + 2 * 64) * 128 * 4 + 1024;    //  97 KB
    const int SM_RNN = 131072 + 3 * 32768 + 1024;             // 225 KB
    cudaFuncSetAttribute(k_g3<32, 64, 2, 4>,
                         cudaFuncAttributeMaxDynamicSharedMemorySize, SM_P);
    cudaFuncSetAttribute(k_fused,
                         cudaFuncAttributeMaxDynamicSharedMemorySize, SM_RNN);

    // 0) operand splits + barrier reset (single kernel)
    k_split_all<<<(HID * HID) / 256, 256>>>(Whh_w, whhhi, whhlos,
                                            Wxh_w, wxhhi, wxhlos,
                                            fc_w, fchi, fclos,
                                            embed, embhi, emblos);

    // 1) P = embed @ Wxh^T + bxh + bhh  (both biases folded)
    k_g3<32, 64, 2, 4><<<dim3(HID / 64, VOCABN / 32), 256, SM_P>>>(
        embhi, emblos, wxhhi, wxhlos, Wxh_b, Whh_b, P);

    // 2) t = 0
    k_step0<<<(BATCHN * HID) / 256, 256>>>(x, P, hhi, hlos);

    // 3) fused persistent: recurrence + tail fc + fc consumers
    k_fused<<<NCTA + NFC, 256, SM_RNN>>>(whhhi, whhlos, P, x, hhi, hlos,
                                         fchi, fclos, fc_b, outp);
}